// round 10
// baseline (speedup 1.0000x reference)
#include <cuda_runtime.h>
#include <cuda_fp16.h>
#include <cstdint>

#define D 128
#define MAXN 100000
#define MAXE 1600000

__device__ __align__(16) __half g_xh[(size_t)MAXN * D];
__device__ __align__(16) __half g_oh[(size_t)MAXN * D];
__device__ __align__(16) __half g_wh[4 * D * D];   // weights [c][k] fp16
__device__ int g_deg[MAXN];
__device__ int g_incl[MAXN];
__device__ int g_bsum[128];
__device__ int g_rowptr[MAXN + 1];
__device__ int g_cursor[MAXN];
__device__ int g_elist[MAXE];

// ---------------------------------------------------------------------------
// prep: convert weights + x to fp16, zero deg — one launch.
__global__ void prep_kernel(const float* __restrict__ x,
                            const float* __restrict__ w0,
                            const float* __restrict__ w1,
                            const float* __restrict__ w2,
                            const float* __restrict__ w3,
                            int n4, int n) {
    int i = blockIdx.x * blockDim.x + threadIdx.x;
    if (i < 4 * D * D) {
        int widx = i >> 14;
        const float* w = (widx == 0) ? w0 : (widx == 1) ? w1 : (widx == 2) ? w2 : w3;
        g_wh[i] = __float2half(w[i & 16383]);
    }
    int j = i - 4 * D * D;
    if (j >= 0 && j < n4) {
        float4 v = __ldg((const float4*)x + j);
        __half2 h0 = __floats2half2_rn(v.x, v.y);
        __half2 h1 = __floats2half2_rn(v.z, v.w);
        uint2 u;
        u.x = *(unsigned*)&h0;
        u.y = *(unsigned*)&h1;
        ((uint2*)g_xh)[j] = u;
    }
    int k = j - n4;
    if (k >= 0 && k < n) g_deg[k] = 0;
}

// ---------------------------------------------------------------------------
// CSR build
__global__ void hist_kernel(const int* __restrict__ ei, int E) {
    int t = blockIdx.x * blockDim.x + threadIdx.x;
    int base = t * 4;
    if (base + 4 <= E) {
        int4 d = __ldg((const int4*)(ei + E) + t);
        atomicAdd(&g_deg[d.x], 1);
        atomicAdd(&g_deg[d.y], 1);
        atomicAdd(&g_deg[d.z], 1);
        atomicAdd(&g_deg[d.w], 1);
    } else {
        for (int e = base; e < E; e++) atomicAdd(&g_deg[__ldg(ei + E + e)], 1);
    }
}

__global__ void scan1_kernel(int n) {
    __shared__ int wsum[32];
    int t = threadIdx.x, b = blockIdx.x;
    int i = b * 1024 + t;
    int lane = t & 31, warp = t >> 5;
    int v = (i < n) ? g_deg[i] : 0;
    int s = v;
#pragma unroll
    for (int off = 1; off < 32; off <<= 1) {
        int u = __shfl_up_sync(0xffffffffu, s, off);
        if (lane >= off) s += u;
    }
    if (lane == 31) wsum[warp] = s;
    __syncthreads();
    if (warp == 0) {
        int ws = wsum[lane];
#pragma unroll
        for (int off = 1; off < 32; off <<= 1) {
            int u = __shfl_up_sync(0xffffffffu, ws, off);
            if (lane >= off) ws += u;
        }
        wsum[lane] = ws;
    }
    __syncthreads();
    int incl = s + (warp > 0 ? wsum[warp - 1] : 0);
    if (i < n) g_incl[i] = incl;
    if (t == 1023) g_bsum[b] = incl;
}

__global__ void scan23_kernel(int n, int E) {
    __shared__ int pre;
    int t = threadIdx.x, b = blockIdx.x;
    if (t < 32) {
        int s = 0;
        for (int j = t; j < b; j += 32) s += g_bsum[j];
#pragma unroll
        for (int off = 16; off; off >>= 1)
            s += __shfl_down_sync(0xffffffffu, s, off);
        if (t == 0) pre = s;
    }
    __syncthreads();
    int i = b * 1024 + t;
    if (i < n) {
        int excl = pre + g_incl[i] - g_deg[i];
        g_rowptr[i] = excl;
        g_cursor[i] = excl;
    }
    if (i == 0) g_rowptr[n] = E;
}

__global__ void fill_kernel(const int* __restrict__ ei, int E) {
    int t = blockIdx.x * blockDim.x + threadIdx.x;
    int base = t * 4;
    if (base + 4 <= E) {
        int4 s = __ldg((const int4*)ei + t);
        int4 d = __ldg((const int4*)(ei + E) + t);
        g_elist[atomicAdd(&g_cursor[d.x], 1)] = s.x;
        g_elist[atomicAdd(&g_cursor[d.y], 1)] = s.y;
        g_elist[atomicAdd(&g_cursor[d.z], 1)] = s.z;
        g_elist[atomicAdd(&g_cursor[d.w], 1)] = s.w;
    } else {
        for (int e = base; e < E; e++) {
            int s = __ldg(ei + e);
            int d = __ldg(ei + E + e);
            g_elist[atomicAdd(&g_cursor[d], 1)] = s;
        }
    }
}

// ---------------------------------------------------------------------------
// Phase-fused layer: gather tile into smem, then dual MMA. Non-persistent,
// grid = ntiles, 2 CTAs/SM for cross-block gather/MMA overlap.
//   out = relu((x[n]+sum_neigh) @ W1^T + b1) @ W2^T + b2
#define XSTR 136
#define WSTR 136
#define TR 128

__device__ __forceinline__ void mma_16x8x16(float* d, const unsigned* a, const unsigned* b) {
    asm volatile(
        "mma.sync.aligned.m16n8k16.row.col.f32.f16.f16.f32 "
        "{%0,%1,%2,%3}, {%4,%5,%6,%7}, {%8,%9}, {%0,%1,%2,%3};"
        : "+f"(d[0]), "+f"(d[1]), "+f"(d[2]), "+f"(d[3])
        : "r"(a[0]), "r"(a[1]), "r"(a[2]), "r"(a[3]), "r"(b[0]), "r"(b[1]));
}

__device__ __forceinline__ void ldsm_x4(unsigned& r0, unsigned& r1,
                                        unsigned& r2, unsigned& r3, unsigned addr) {
    asm volatile("ldmatrix.sync.aligned.m8n8.x4.shared.b16 {%0,%1,%2,%3}, [%4];"
                 : "=r"(r0), "=r"(r1), "=r"(r2), "=r"(r3) : "r"(addr));
}

__device__ __forceinline__ void facc(float4& a, uint2 u) {
    float2 f0 = __half22float2(*(__half2*)&u.x);
    float2 f1 = __half22float2(*(__half2*)&u.y);
    a.x += f0.x; a.y += f0.y; a.z += f1.x; a.w += f1.y;
}

__global__ __launch_bounds__(256, 2)
void layer_phase_kernel(const __half* __restrict__ xin,   // gather source
                        const __half* __restrict__ w1,    // [c][k]
                        const float* __restrict__ b1,
                        const __half* __restrict__ w2,    // [c][k]
                        const float* __restrict__ b2,
                        __half* __restrict__ outh,
                        float* __restrict__ outf,
                        int nrows) {
    extern __shared__ __half smh[];
    __half* Ws1 = smh;                        // [128][WSTR]
    __half* Ws2 = smh + 128 * WSTR;           // [128][WSTR]
    __half* Xs  = smh + 2 * 128 * WSTR;       // [128][XSTR]
    float*  Bs1 = (float*)(Xs + TR * XSTR);   // [128]
    float*  Bs2 = Bs1 + 128;                  // [128]

    int tid = threadIdx.x;
    int warp = tid >> 5, lane = tid & 31;

    // Stage W panels + biases (used after the phase barrier)
    for (int i = tid; i < 128 * 16; i += 256) {
        int c = i >> 4, seg = i & 15;
        *(uint4*)(Ws1 + c * WSTR + seg * 8) = __ldg((const uint4*)w1 + i);
        *(uint4*)(Ws2 + c * WSTR + seg * 8) = __ldg((const uint4*)w2 + i);
    }
    if (tid < 128) {
        Bs1[tid] = __ldg(b1 + tid);
        Bs2[tid] = __ldg(b2 + tid);
    }

    // ---- Phase 1: gather 128 nodes into Xs (warp w -> rows w*16..w*16+15) --
    {
        const uint2* x2 = (const uint2*)xin;
        long long n0 = (long long)blockIdx.x * TR + warp * 16;
        for (int n = 0; n < 16; n++) {
            long long node = n0 + n;
            float4 acc = make_float4(0.f, 0.f, 0.f, 0.f);
            if (node < nrows) {
                facc(acc, __ldg(x2 + node * 32 + lane));
                int beg = __ldg(g_rowptr + node);
                int end = __ldg(g_rowptr + node + 1);
                int i = beg;
                for (; i + 8 <= end; i += 8) {
                    uint2 v0 = __ldg(x2 + (long long)__ldg(g_elist + i)     * 32 + lane);
                    uint2 v1 = __ldg(x2 + (long long)__ldg(g_elist + i + 1) * 32 + lane);
                    uint2 v2 = __ldg(x2 + (long long)__ldg(g_elist + i + 2) * 32 + lane);
                    uint2 v3 = __ldg(x2 + (long long)__ldg(g_elist + i + 3) * 32 + lane);
                    uint2 v4 = __ldg(x2 + (long long)__ldg(g_elist + i + 4) * 32 + lane);
                    uint2 v5 = __ldg(x2 + (long long)__ldg(g_elist + i + 5) * 32 + lane);
                    uint2 v6 = __ldg(x2 + (long long)__ldg(g_elist + i + 6) * 32 + lane);
                    uint2 v7 = __ldg(x2 + (long long)__ldg(g_elist + i + 7) * 32 + lane);
                    facc(acc, v0); facc(acc, v1); facc(acc, v2); facc(acc, v3);
                    facc(acc, v4); facc(acc, v5); facc(acc, v6); facc(acc, v7);
                }
                for (; i < end; i++)
                    facc(acc, __ldg(x2 + (long long)__ldg(g_elist + i) * 32 + lane));
            }
            __half2 h0 = __floats2half2_rn(acc.x, acc.y);
            __half2 h1 = __floats2half2_rn(acc.z, acc.w);
            uint2 u;
            u.x = *(unsigned*)&h0;
            u.y = *(unsigned*)&h1;
            *(uint2*)(Xs + (warp * 16 + n) * XSTR + lane * 4) = u;
        }
    }
    __syncthreads();

    // ---- Phase 2: dual MMA on 16-row stripe ----
    int gi = lane >> 2, ti = lane & 3;
    int mbase = warp * 16;

    int a_row = mbase + (lane & 7) + (((lane >> 3) & 1) << 3);
    int a_koff = (lane >> 4) << 3;
    int b_row = (lane & 7) + ((lane >> 4) << 3);
    int b_koff = ((lane >> 3) & 1) << 3;

    unsigned ws1_base = (unsigned)__cvta_generic_to_shared(Ws1);
    unsigned ws2_base = (unsigned)__cvta_generic_to_shared(Ws2);
    unsigned xs_base  = (unsigned)__cvta_generic_to_shared(Xs);
    unsigned b_off = (b_row * WSTR + b_koff) * 2;
    unsigned a_off = (a_row * XSTR + a_koff) * 2;

    float acc1[16][4];
#pragma unroll
    for (int j = 0; j < 16; j++)
#pragma unroll
        for (int q = 0; q < 4; q++) acc1[j][q] = 0.f;

#pragma unroll
    for (int kk = 0; kk < 8; kk++) {
        int k0 = kk * 16;
        unsigned a[4];
        ldsm_x4(a[0], a[1], a[2], a[3], xs_base + a_off + k0 * 2);
#pragma unroll
        for (int j = 0; j < 16; j += 2) {
            unsigned r0, r1, r2, r3;
            ldsm_x4(r0, r1, r2, r3, ws1_base + b_off + (j * 8 * WSTR + k0) * 2);
            unsigned bj0[2] = {r0, r1};
            unsigned bj1[2] = {r2, r3};
            mma_16x8x16(acc1[j], a, bj0);
            mma_16x8x16(acc1[j + 1], a, bj1);
        }
    }

    unsigned af[16][2];
#pragma unroll
    for (int j = 0; j < 16; j++) {
        int c0 = j * 8 + 2 * ti;
        float bx = Bs1[c0], by = Bs1[c0 + 1];
        float v0 = fmaxf(acc1[j][0] + bx, 0.f);
        float v1 = fmaxf(acc1[j][1] + by, 0.f);
        float v2 = fmaxf(acc1[j][2] + bx, 0.f);
        float v3 = fmaxf(acc1[j][3] + by, 0.f);
        __half2 lo = __floats2half2_rn(v0, v1);
        __half2 hi = __floats2half2_rn(v2, v3);
        af[j][0] = *(unsigned*)&lo;
        af[j][1] = *(unsigned*)&hi;
    }

    float acc2[16][4];
#pragma unroll
    for (int j = 0; j < 16; j++)
#pragma unroll
        for (int q = 0; q < 4; q++) acc2[j][q] = 0.f;

#pragma unroll
    for (int kk = 0; kk < 8; kk++) {
        int k0 = kk * 16;
        unsigned a[4] = {af[2 * kk][0], af[2 * kk][1],
                         af[2 * kk + 1][0], af[2 * kk + 1][1]};
#pragma unroll
        for (int j = 0; j < 16; j += 2) {
            unsigned r0, r1, r2, r3;
            ldsm_x4(r0, r1, r2, r3, ws2_base + b_off + (j * 8 * WSTR + k0) * 2);
            unsigned bj0[2] = {r0, r1};
            unsigned bj1[2] = {r2, r3};
            mma_16x8x16(acc2[j], a, bj0);
            mma_16x8x16(acc2[j + 1], a, bj1);
        }
    }

    long long row0 = (long long)blockIdx.x * TR + mbase + gi;
#pragma unroll
    for (int j = 0; j < 16; j++) {
        int c0 = j * 8 + 2 * ti;
        float bx = Bs2[c0], by = Bs2[c0 + 1];
        float v0 = acc2[j][0] + bx;
        float v1 = acc2[j][1] + by;
        float v2 = acc2[j][2] + bx;
        float v3 = acc2[j][3] + by;
        if (outf) {
            if (row0 < nrows)
                *(float2*)(outf + row0 * D + c0) = make_float2(v0, v1);
            if (row0 + 8 < nrows)
                *(float2*)(outf + (row0 + 8) * D + c0) = make_float2(v2, v3);
        } else {
            if (row0 < nrows)
                *(__half2*)(outh + row0 * D + c0) = __floats2half2_rn(v0, v1);
            if (row0 + 8 < nrows)
                *(__half2*)(outh + (row0 + 8) * D + c0) = __floats2half2_rn(v2, v3);
        }
    }
}

// ---------------------------------------------------------------------------
extern "C" void kernel_launch(void* const* d_in, const int* in_sizes, int n_in,
                              void* d_out, int out_size) {
    const float* x   = (const float*)d_in[0];
    const int*   ei  = (const int*)d_in[1];
    const float* w0a = (const float*)d_in[2];
    const float* b0a = (const float*)d_in[3];
    const float* w0b = (const float*)d_in[4];
    const float* b0b = (const float*)d_in[5];
    const float* w1a = (const float*)d_in[6];
    const float* b1a = (const float*)d_in[7];
    const float* w1b = (const float*)d_in[8];
    const float* b1b = (const float*)d_in[9];

    int N = in_sizes[0] / D;
    int E = in_sizes[1] / 2;

    __half *p_xh, *p_oh, *p_wh;
    cudaGetSymbolAddress((void**)&p_xh, g_xh);
    cudaGetSymbolAddress((void**)&p_oh, g_oh);
    cudaGetSymbolAddress((void**)&p_wh, g_wh);

    const int smem = (2 * 128 * WSTR + TR * XSTR) * (int)sizeof(__half)
                   + 256 * (int)sizeof(float);
    cudaFuncSetAttribute(layer_phase_kernel, cudaFuncAttributeMaxDynamicSharedMemorySize, smem);

    int nb = (N + 1023) / 1024;
    int n4 = N * (D / 4);
    int e4 = (E + 3) / 4;
    int prepTotal = 4 * D * D + n4 + N;
    int ntiles = (N + TR - 1) / TR;

    prep_kernel<<<(prepTotal + 255) / 256, 256>>>(x, w0a, w0b, w1a, w1b, n4, N);

    // ---- CSR build ----
    hist_kernel<<<(e4 + 255) / 256, 256>>>(ei, E);
    scan1_kernel<<<nb, 1024>>>(N);
    scan23_kernel<<<nb, 1024>>>(N, E);
    fill_kernel<<<(e4 + 255) / 256, 256>>>(ei, E);

    // ---- Layer 1 (gather from x, out fp16) ----
    layer_phase_kernel<<<ntiles, 256, smem>>>(p_xh, p_wh + 0 * D * D, b0a,
                                              p_wh + 1 * D * D, b0b, p_oh, nullptr, N);
    // ---- Layer 2 (gather from layer-1 out, out fp32 to d_out) ----
    layer_phase_kernel<<<ntiles, 256, smem>>>(p_oh, p_wh + 2 * D * D, b1a,
                                              p_wh + 3 * D * D, b1b, nullptr, (float*)d_out, N);
}

// round 11
// speedup vs baseline: 1.4037x; 1.4037x over previous
#include <cuda_runtime.h>
#include <cuda_fp16.h>
#include <cstdint>

#define D 128
#define MAXN 100000
#define MAXE 1600000

__device__ __align__(16) __half g_xh[(size_t)MAXN * D];
__device__ __align__(16) __half g_hh[(size_t)MAXN * D];
__device__ __align__(16) __half g_oh[(size_t)MAXN * D];
__device__ __align__(16) __half g_wh[4 * D * D];   // weights [c][k] fp16
__device__ int g_deg[MAXN];
__device__ int g_incl[MAXN];
__device__ int g_bsum[128];
__device__ int g_rowptr[MAXN + 1];
__device__ int g_cursor[MAXN];
__device__ int g_elist[MAXE];

// ---------------------------------------------------------------------------
// prep: convert weights + x to fp16, zero deg — one launch.
__global__ void prep_kernel(const float* __restrict__ x,
                            const float* __restrict__ w0,
                            const float* __restrict__ w1,
                            const float* __restrict__ w2,
                            const float* __restrict__ w3,
                            int n4, int n) {
    int i = blockIdx.x * blockDim.x + threadIdx.x;
    if (i < 4 * D * D) {
        int widx = i >> 14;
        const float* w = (widx == 0) ? w0 : (widx == 1) ? w1 : (widx == 2) ? w2 : w3;
        g_wh[i] = __float2half(w[i & 16383]);
    }
    int j = i - 4 * D * D;
    if (j >= 0 && j < n4) {
        float4 v = __ldg((const float4*)x + j);
        __half2 h0 = __floats2half2_rn(v.x, v.y);
        __half2 h1 = __floats2half2_rn(v.z, v.w);
        uint2 u;
        u.x = *(unsigned*)&h0;
        u.y = *(unsigned*)&h1;
        ((uint2*)g_xh)[j] = u;
    }
    int k = j - n4;
    if (k >= 0 && k < n) g_deg[k] = 0;
}

// ---------------------------------------------------------------------------
// CSR build
__global__ void hist_kernel(const int* __restrict__ ei, int E) {
    int t = blockIdx.x * blockDim.x + threadIdx.x;
    int base = t * 4;
    if (base + 4 <= E) {
        int4 d = __ldg((const int4*)(ei + E) + t);
        atomicAdd(&g_deg[d.x], 1);
        atomicAdd(&g_deg[d.y], 1);
        atomicAdd(&g_deg[d.z], 1);
        atomicAdd(&g_deg[d.w], 1);
    } else {
        for (int e = base; e < E; e++) atomicAdd(&g_deg[__ldg(ei + E + e)], 1);
    }
}

__global__ void scan1_kernel(int n) {
    __shared__ int wsum[32];
    int t = threadIdx.x, b = blockIdx.x;
    int i = b * 1024 + t;
    int lane = t & 31, warp = t >> 5;
    int v = (i < n) ? g_deg[i] : 0;
    int s = v;
#pragma unroll
    for (int off = 1; off < 32; off <<= 1) {
        int u = __shfl_up_sync(0xffffffffu, s, off);
        if (lane >= off) s += u;
    }
    if (lane == 31) wsum[warp] = s;
    __syncthreads();
    if (warp == 0) {
        int ws = wsum[lane];
#pragma unroll
        for (int off = 1; off < 32; off <<= 1) {
            int u = __shfl_up_sync(0xffffffffu, ws, off);
            if (lane >= off) ws += u;
        }
        wsum[lane] = ws;
    }
    __syncthreads();
    int incl = s + (warp > 0 ? wsum[warp - 1] : 0);
    if (i < n) g_incl[i] = incl;
    if (t == 1023) g_bsum[b] = incl;
}

__global__ void scan23_kernel(int n, int E) {
    __shared__ int pre;
    int t = threadIdx.x, b = blockIdx.x;
    if (t < 32) {
        int s = 0;
        for (int j = t; j < b; j += 32) s += g_bsum[j];
#pragma unroll
        for (int off = 16; off; off >>= 1)
            s += __shfl_down_sync(0xffffffffu, s, off);
        if (t == 0) pre = s;
    }
    __syncthreads();
    int i = b * 1024 + t;
    if (i < n) {
        int excl = pre + g_incl[i] - g_deg[i];
        g_rowptr[i] = excl;
        g_cursor[i] = excl;
    }
    if (i == 0) g_rowptr[n] = E;
}

__global__ void fill_kernel(const int* __restrict__ ei, int E) {
    int t = blockIdx.x * blockDim.x + threadIdx.x;
    int base = t * 4;
    if (base + 4 <= E) {
        int4 s = __ldg((const int4*)ei + t);
        int4 d = __ldg((const int4*)(ei + E) + t);
        g_elist[atomicAdd(&g_cursor[d.x], 1)] = s.x;
        g_elist[atomicAdd(&g_cursor[d.y], 1)] = s.y;
        g_elist[atomicAdd(&g_cursor[d.z], 1)] = s.z;
        g_elist[atomicAdd(&g_cursor[d.w], 1)] = s.w;
    } else {
        for (int e = base; e < E; e++) {
            int s = __ldg(ei + e);
            int d = __ldg(ei + E + e);
            g_elist[atomicAdd(&g_cursor[d], 1)] = s;
        }
    }
}

// ---------------------------------------------------------------------------
// Gather: h[n] = x[n] + sum_{s in N(n)} x[s].  One warp per node (standalone —
// fusing this into the MLP regressed twice; the HW scheduler's load balancing
// across 12.5K blocks is load-bearing).
__device__ __forceinline__ void acc_add(float4& a, uint2 u) {
    float2 f0 = __half22float2(*(__half2*)&u.x);
    float2 f1 = __half22float2(*(__half2*)&u.y);
    a.x += f0.x; a.y += f0.y; a.z += f1.x; a.w += f1.y;
}

__global__ void gather_h_kernel(const __half* __restrict__ xin,
                                __half* __restrict__ hout, int N) {
    int w = (int)((blockIdx.x * (unsigned)blockDim.x + threadIdx.x) >> 5);
    if (w >= N) return;
    int lane = threadIdx.x & 31;
    const uint2* x2 = (const uint2*)xin;
    float4 acc = make_float4(0.f, 0.f, 0.f, 0.f);
    acc_add(acc, __ldg(x2 + (long long)w * 32 + lane));
    int beg = __ldg(g_rowptr + w);
    int end = __ldg(g_rowptr + w + 1);
    int i = beg;
    for (; i + 4 <= end; i += 4) {
        int s0 = __ldg(g_elist + i);
        int s1 = __ldg(g_elist + i + 1);
        int s2 = __ldg(g_elist + i + 2);
        int s3 = __ldg(g_elist + i + 3);
        uint2 v0 = __ldg(x2 + (long long)s0 * 32 + lane);
        uint2 v1 = __ldg(x2 + (long long)s1 * 32 + lane);
        uint2 v2 = __ldg(x2 + (long long)s2 * 32 + lane);
        uint2 v3 = __ldg(x2 + (long long)s3 * 32 + lane);
        acc_add(acc, v0); acc_add(acc, v1); acc_add(acc, v2); acc_add(acc, v3);
    }
    for (; i < end; i++) {
        int s0 = __ldg(g_elist + i);
        acc_add(acc, __ldg(x2 + (long long)s0 * 32 + lane));
    }
    __half2 h0 = __floats2half2_rn(acc.x, acc.y);
    __half2 h1 = __floats2half2_rn(acc.z, acc.w);
    uint2 u;
    u.x = *(unsigned*)&h0;
    u.y = *(unsigned*)&h1;
    ((uint2*)hout)[(long long)w * 32 + lane] = u;
}

// ---------------------------------------------------------------------------
// Fused layer: out = relu(X @ W1^T + b1) @ W2^T + b2   (persistent, fp16 MMA)
// 2 CTAs/SM: T bounces through the warp's own 16 rows of Xs (warp-private,
// only __syncwarp needed), register peak ~110, single X buffer (103KB smem).
#define XSTR 136
#define WSTR 136
#define TR 128

__device__ __forceinline__ void mma_16x8x16(float* d, const unsigned* a, const unsigned* b) {
    asm volatile(
        "mma.sync.aligned.m16n8k16.row.col.f32.f16.f16.f32 "
        "{%0,%1,%2,%3}, {%4,%5,%6,%7}, {%8,%9}, {%0,%1,%2,%3};"
        : "+f"(d[0]), "+f"(d[1]), "+f"(d[2]), "+f"(d[3])
        : "r"(a[0]), "r"(a[1]), "r"(a[2]), "r"(a[3]), "r"(b[0]), "r"(b[1]));
}

__device__ __forceinline__ void ldsm_x4(unsigned& r0, unsigned& r1,
                                        unsigned& r2, unsigned& r3, unsigned addr) {
    asm volatile("ldmatrix.sync.aligned.m8n8.x4.shared.b16 {%0,%1,%2,%3}, [%4];"
                 : "=r"(r0), "=r"(r1), "=r"(r2), "=r"(r3) : "r"(addr));
}

__global__ __launch_bounds__(256, 2)
void layer_fused_kernel(const __half* __restrict__ in,
                        const __half* __restrict__ w1,   // [c][k]
                        const float* __restrict__ b1,
                        const __half* __restrict__ w2,   // [c][k]
                        const float* __restrict__ b2,
                        __half* __restrict__ outh,
                        float* __restrict__ outf,
                        int nrows) {
    extern __shared__ __half smh[];
    __half* Ws1 = smh;                        // [128][WSTR]
    __half* Ws2 = smh + 128 * WSTR;           // [128][WSTR]
    __half* Xs  = smh + 2 * 128 * WSTR;       // [128][XSTR] (X, then T in-place)
    float*  Bs1 = (float*)(Xs + TR * XSTR);   // [128]
    float*  Bs2 = Bs1 + 128;                  // [128]

    int tid = threadIdx.x;

    // Stage W panels + biases
    for (int i = tid; i < 128 * 16; i += 256) {
        int c = i >> 4, seg = i & 15;
        *(uint4*)(Ws1 + c * WSTR + seg * 8) = __ldg((const uint4*)w1 + i);
        *(uint4*)(Ws2 + c * WSTR + seg * 8) = __ldg((const uint4*)w2 + i);
    }
    if (tid < 128) {
        Bs1[tid] = __ldg(b1 + tid);
        Bs2[tid] = __ldg(b2 + tid);
    }

    int warp = tid >> 5, lane = tid & 31;
    int gi = lane >> 2, ti = lane & 3;
    int mbase = warp * 16;

    // ldmatrix per-lane address offsets
    int a_row = mbase + (lane & 7) + (((lane >> 3) & 1) << 3);
    int a_koff = (lane >> 4) << 3;
    int b_row = (lane & 7) + ((lane >> 4) << 3);
    int b_koff = ((lane >> 3) & 1) << 3;

    unsigned ws1_base = (unsigned)__cvta_generic_to_shared(Ws1);
    unsigned ws2_base = (unsigned)__cvta_generic_to_shared(Ws2);
    unsigned xs_base  = (unsigned)__cvta_generic_to_shared(Xs);
    unsigned b_off = (b_row * WSTR + b_koff) * 2;
    unsigned a_off = (a_row * XSTR + a_koff) * 2;

    int ntiles = (nrows + TR - 1) / TR;
    int stride = gridDim.x;

    for (int tt = blockIdx.x; tt < ntiles; tt += stride) {
        // ---- stage X tile (all warps done with previous T before overwrite)
        __syncthreads();
        {
            long long r0 = (long long)tt * TR;
#pragma unroll
            for (int p = 0; p < 8; p++) {
                int idx = tid + 256 * p;
                long long gr = r0 + (idx >> 4);
                uint4 v = (gr < nrows) ? __ldg((const uint4*)in + gr * 16 + (idx & 15))
                                       : make_uint4(0, 0, 0, 0);
                *(uint4*)(Xs + (idx >> 4) * XSTR + (idx & 15) * 8) = v;
            }
        }
        __syncthreads();

        // ---- MMA1: T[16 rows][128 cols] ----
        float acc1[16][4];
#pragma unroll
        for (int j = 0; j < 16; j++)
#pragma unroll
            for (int q = 0; q < 4; q++) acc1[j][q] = 0.f;

#pragma unroll
        for (int kk = 0; kk < 8; kk++) {
            int k0 = kk * 16;
            unsigned a[4];
            ldsm_x4(a[0], a[1], a[2], a[3], xs_base + a_off + k0 * 2);
#pragma unroll
            for (int j = 0; j < 16; j += 2) {
                unsigned r0, r1, r2, r3;
                ldsm_x4(r0, r1, r2, r3, ws1_base + b_off + (j * 8 * WSTR + k0) * 2);
                unsigned bj0[2] = {r0, r1};
                unsigned bj1[2] = {r2, r3};
                mma_16x8x16(acc1[j], a, bj0);
                mma_16x8x16(acc1[j + 1], a, bj1);
            }
        }

        // ---- bias1 + relu + store T into OWN rows of Xs (warp-private) ----
        {
            int r0 = mbase + gi;
#pragma unroll
            for (int j = 0; j < 16; j++) {
                int c0 = j * 8 + 2 * ti;
                float bx = Bs1[c0], by = Bs1[c0 + 1];
                float v0 = fmaxf(acc1[j][0] + bx, 0.f);
                float v1 = fmaxf(acc1[j][1] + by, 0.f);
                float v2 = fmaxf(acc1[j][2] + bx, 0.f);
                float v3 = fmaxf(acc1[j][3] + by, 0.f);
                __half2 lo = __floats2half2_rn(v0, v1);
                __half2 hi = __floats2half2_rn(v2, v3);
                *(__half2*)(Xs + r0 * XSTR + c0) = lo;
                *(__half2*)(Xs + (r0 + 8) * XSTR + c0) = hi;
            }
        }
        __syncwarp();

        // ---- MMA2: out = T @ W2^T (A-frags re-loaded from Xs) ----
        float acc2[16][4];
#pragma unroll
        for (int j = 0; j < 16; j++)
#pragma unroll
            for (int q = 0; q < 4; q++) acc2[j][q] = 0.f;

#pragma unroll
        for (int kk = 0; kk < 8; kk++) {
            int k0 = kk * 16;
            unsigned a[4];
            ldsm_x4(a[0], a[1], a[2], a[3], xs_base + a_off + k0 * 2);
#pragma unroll
            for (int j = 0; j < 16; j += 2) {
                unsigned r0, r1, r2, r3;
                ldsm_x4(r0, r1, r2, r3, ws2_base + b_off + (j * 8 * WSTR + k0) * 2);
                unsigned bj0[2] = {r0, r1};
                unsigned bj1[2] = {r2, r3};
                mma_16x8x16(acc2[j], a, bj0);
                mma_16x8x16(acc2[j + 1], a, bj1);
            }
        }

        // ---- epilogue: bias2, store ----
        long long row0 = (long long)tt * TR + mbase + gi;
#pragma unroll
        for (int j = 0; j < 16; j++) {
            int c0 = j * 8 + 2 * ti;
            float bx = Bs2[c0], by = Bs2[c0 + 1];
            float v0 = acc2[j][0] + bx;
            float v1 = acc2[j][1] + by;
            float v2 = acc2[j][2] + bx;
            float v3 = acc2[j][3] + by;
            if (outf) {
                if (row0 < nrows)
                    *(float2*)(outf + row0 * D + c0) = make_float2(v0, v1);
                if (row0 + 8 < nrows)
                    *(float2*)(outf + (row0 + 8) * D + c0) = make_float2(v2, v3);
            } else {
                if (row0 < nrows)
                    *(__half2*)(outh + row0 * D + c0) = __floats2half2_rn(v0, v1);
                if (row0 + 8 < nrows)
                    *(__half2*)(outh + (row0 + 8) * D + c0) = __floats2half2_rn(v2, v3);
            }
        }
    }
}

// ---------------------------------------------------------------------------
extern "C" void kernel_launch(void* const* d_in, const int* in_sizes, int n_in,
                              void* d_out, int out_size) {
    const float* x   = (const float*)d_in[0];
    const int*   ei  = (const int*)d_in[1];
    const float* w0a = (const float*)d_in[2];
    const float* b0a = (const float*)d_in[3];
    const float* w0b = (const float*)d_in[4];
    const float* b0b = (const float*)d_in[5];
    const float* w1a = (const float*)d_in[6];
    const float* b1a = (const float*)d_in[7];
    const float* w1b = (const float*)d_in[8];
    const float* b1b = (const float*)d_in[9];

    int N = in_sizes[0] / D;
    int E = in_sizes[1] / 2;

    __half *p_xh, *p_hh, *p_oh, *p_wh;
    cudaGetSymbolAddress((void**)&p_xh, g_xh);
    cudaGetSymbolAddress((void**)&p_hh, g_hh);
    cudaGetSymbolAddress((void**)&p_oh, g_oh);
    cudaGetSymbolAddress((void**)&p_wh, g_wh);

    int nsm = 148;
    cudaDeviceGetAttribute(&nsm, cudaDevAttrMultiProcessorCount, 0);

    const int smem = (2 * 128 * WSTR + TR * XSTR) * (int)sizeof(__half)
                   + 256 * (int)sizeof(float);
    cudaFuncSetAttribute(layer_fused_kernel, cudaFuncAttributeMaxDynamicSharedMemorySize, smem);

    int nb = (N + 1023) / 1024;
    int gatherBlocks = (N + 7) / 8;
    int n4 = N * (D / 4);
    int e4 = (E + 3) / 4;
    int prepTotal = 4 * D * D + n4 + N;

    prep_kernel<<<(prepTotal + 255) / 256, 256>>>(x, w0a, w0b, w1a, w1b, n4, N);

    // ---- CSR build ----
    hist_kernel<<<(e4 + 255) / 256, 256>>>(ei, E);
    scan1_kernel<<<nb, 1024>>>(N);
    scan23_kernel<<<nb, 1024>>>(N, E);
    fill_kernel<<<(e4 + 255) / 256, 256>>>(ei, E);

    // ---- Layer 1 ----
    gather_h_kernel<<<gatherBlocks, 256>>>(p_xh, p_hh, N);
    layer_fused_kernel<<<2 * nsm, 256, smem>>>(p_hh, p_wh + 0 * D * D, b0a,
                                               p_wh + 1 * D * D, b0b, p_oh, nullptr, N);

    // ---- Layer 2 ----
    gather_h_kernel<<<gatherBlocks, 256>>>(p_oh, p_hh, N);
    layer_fused_kernel<<<2 * nsm, 256, smem>>>(p_hh, p_wh + 2 * D * D, b1a,
                                               p_wh + 3 * D * D, b1b, nullptr, (float*)d_out, N);
}

// round 12
// speedup vs baseline: 1.4835x; 1.0569x over previous
#include <cuda_runtime.h>
#include <cuda_fp16.h>
#include <cstdint>

#define D 128
#define MAXN 100000
#define MAXE 1600000

#define PDL_TRIGGER() asm volatile("griddepcontrol.launch_dependents;" ::: "memory")
#define PDL_WAIT()    asm volatile("griddepcontrol.wait;" ::: "memory")

__device__ __align__(16) __half g_xh[(size_t)MAXN * D];
__device__ __align__(16) __half g_hh[(size_t)MAXN * D];
__device__ __align__(16) __half g_oh[(size_t)MAXN * D];
__device__ __align__(16) __half g_wh[4 * D * D];   // weights [c][k] fp16
__device__ int g_deg[MAXN];
__device__ int g_incl[MAXN];
__device__ int g_bsum[128];
__device__ int g_rowptr[MAXN + 1];
__device__ int g_cursor[MAXN];
__device__ int g_elist[MAXE];

// ---------------------------------------------------------------------------
// prep: convert weights + x to fp16, zero deg. First kernel; gates the whole
// PDL cascade by COMPLETION (never triggers early) — this is what makes the
// MLP kernels' pre-wait W-panel preamble safe.
__global__ void prep_kernel(const float* __restrict__ x,
                            const float* __restrict__ w0,
                            const float* __restrict__ w1,
                            const float* __restrict__ w2,
                            const float* __restrict__ w3,
                            int n4, int n) {
    int i = blockIdx.x * blockDim.x + threadIdx.x;
    if (i < 4 * D * D) {
        int widx = i >> 14;
        const float* w = (widx == 0) ? w0 : (widx == 1) ? w1 : (widx == 2) ? w2 : w3;
        g_wh[i] = __float2half(w[i & 16383]);
    }
    int j = i - 4 * D * D;
    if (j >= 0 && j < n4) {
        float4 v = __ldg((const float4*)x + j);
        __half2 h0 = __floats2half2_rn(v.x, v.y);
        __half2 h1 = __floats2half2_rn(v.z, v.w);
        uint2 u;
        u.x = *(unsigned*)&h0;
        u.y = *(unsigned*)&h1;
        ((uint2*)g_xh)[j] = u;
    }
    int k = j - n4;
    if (k >= 0 && k < n) g_deg[k] = 0;
}

// ---------------------------------------------------------------------------
// CSR build
__global__ void hist_kernel(const int* __restrict__ ei, int E) {
    PDL_TRIGGER();               // plain-launched (after prep completes)
    int t = blockIdx.x * blockDim.x + threadIdx.x;
    int base = t * 4;
    if (base + 4 <= E) {
        int4 d = __ldg((const int4*)(ei + E) + t);
        atomicAdd(&g_deg[d.x], 1);
        atomicAdd(&g_deg[d.y], 1);
        atomicAdd(&g_deg[d.z], 1);
        atomicAdd(&g_deg[d.w], 1);
    } else {
        for (int e = base; e < E; e++) atomicAdd(&g_deg[__ldg(ei + E + e)], 1);
    }
}

__global__ void scan1_kernel(int n) {
    PDL_WAIT();
    PDL_TRIGGER();
    __shared__ int wsum[32];
    int t = threadIdx.x, b = blockIdx.x;
    int i = b * 1024 + t;
    int lane = t & 31, warp = t >> 5;
    int v = (i < n) ? g_deg[i] : 0;
    int s = v;
#pragma unroll
    for (int off = 1; off < 32; off <<= 1) {
        int u = __shfl_up_sync(0xffffffffu, s, off);
        if (lane >= off) s += u;
    }
    if (lane == 31) wsum[warp] = s;
    __syncthreads();
    if (warp == 0) {
        int ws = wsum[lane];
#pragma unroll
        for (int off = 1; off < 32; off <<= 1) {
            int u = __shfl_up_sync(0xffffffffu, ws, off);
            if (lane >= off) ws += u;
        }
        wsum[lane] = ws;
    }
    __syncthreads();
    int incl = s + (warp > 0 ? wsum[warp - 1] : 0);
    if (i < n) g_incl[i] = incl;
    if (t == 1023) g_bsum[b] = incl;
}

__global__ void scan23_kernel(int n, int E) {
    PDL_WAIT();
    PDL_TRIGGER();
    __shared__ int pre;
    int t = threadIdx.x, b = blockIdx.x;
    if (t < 32) {
        int s = 0;
        for (int j = t; j < b; j += 32) s += g_bsum[j];
#pragma unroll
        for (int off = 16; off; off >>= 1)
            s += __shfl_down_sync(0xffffffffu, s, off);
        if (t == 0) pre = s;
    }
    __syncthreads();
    int i = b * 1024 + t;
    if (i < n) {
        int excl = pre + g_incl[i] - g_deg[i];
        g_rowptr[i] = excl;
        g_cursor[i] = excl;
    }
    if (i == 0) g_rowptr[n] = E;
}

__global__ void fill_kernel(const int* __restrict__ ei, int E) {
    PDL_WAIT();
    PDL_TRIGGER();
    int t = blockIdx.x * blockDim.x + threadIdx.x;
    int base = t * 4;
    if (base + 4 <= E) {
        int4 s = __ldg((const int4*)ei + t);
        int4 d = __ldg((const int4*)(ei + E) + t);
        g_elist[atomicAdd(&g_cursor[d.x], 1)] = s.x;
        g_elist[atomicAdd(&g_cursor[d.y], 1)] = s.y;
        g_elist[atomicAdd(&g_cursor[d.z], 1)] = s.z;
        g_elist[atomicAdd(&g_cursor[d.w], 1)] = s.w;
    } else {
        for (int e = base; e < E; e++) {
            int s = __ldg(ei + e);
            int d = __ldg(ei + E + e);
            g_elist[atomicAdd(&g_cursor[d], 1)] = s;
        }
    }
}

// ---------------------------------------------------------------------------
// Gather: h[n] = x[n] + sum_{s in N(n)} x[s].  One warp per node (standalone —
// fusing into the MLP regressed twice; scheduler load-balancing is load-bearing).
__device__ __forceinline__ void acc_add(float4& a, uint2 u) {
    float2 f0 = __half22float2(*(__half2*)&u.x);
    float2 f1 = __half22float2(*(__half2*)&u.y);
    a.x += f0.x; a.y += f0.y; a.z += f1.x; a.w += f1.y;
}

__global__ void gather_h_kernel(const __half* __restrict__ xin,
                                __half* __restrict__ hout, int N) {
    PDL_WAIT();
    PDL_TRIGGER();
    int w = (int)((blockIdx.x * (unsigned)blockDim.x + threadIdx.x) >> 5);
    if (w >= N) return;
    int lane = threadIdx.x & 31;
    const uint2* x2 = (const uint2*)xin;
    float4 acc = make_float4(0.f, 0.f, 0.f, 0.f);
    acc_add(acc, __ldg(x2 + (long long)w * 32 + lane));
    int beg = __ldg(g_rowptr + w);
    int end = __ldg(g_rowptr + w + 1);
    int i = beg;
    for (; i + 4 <= end; i += 4) {
        int s0 = __ldg(g_elist + i);
        int s1 = __ldg(g_elist + i + 1);
        int s2 = __ldg(g_elist + i + 2);
        int s3 = __ldg(g_elist + i + 3);
        uint2 v0 = __ldg(x2 + (long long)s0 * 32 + lane);
        uint2 v1 = __ldg(x2 + (long long)s1 * 32 + lane);
        uint2 v2 = __ldg(x2 + (long long)s2 * 32 + lane);
        uint2 v3 = __ldg(x2 + (long long)s3 * 32 + lane);
        acc_add(acc, v0); acc_add(acc, v1); acc_add(acc, v2); acc_add(acc, v3);
    }
    for (; i < end; i++) {
        int s0 = __ldg(g_elist + i);
        acc_add(acc, __ldg(x2 + (long long)s0 * 32 + lane));
    }
    __half2 h0 = __floats2half2_rn(acc.x, acc.y);
    __half2 h1 = __floats2half2_rn(acc.z, acc.w);
    uint2 u;
    u.x = *(unsigned*)&h0;
    u.y = *(unsigned*)&h1;
    ((uint2*)hout)[(long long)w * 32 + lane] = u;
}

// ---------------------------------------------------------------------------
// Fused layer (R9 register-resident version): out = relu(X@W1^T+b1)@W2^T+b2.
// Persistent, 148 blocks, double-buffered X tiles, ldmatrix fragment loads.
// PDL: trigger at entry; W/bias preamble BEFORE the wait (overlaps gather tail).
#define XSTR 136
#define WSTR 136
#define TR 128

__device__ __forceinline__ void mma_16x8x16(float* d, const unsigned* a, const unsigned* b) {
    asm volatile(
        "mma.sync.aligned.m16n8k16.row.col.f32.f16.f16.f32 "
        "{%0,%1,%2,%3}, {%4,%5,%6,%7}, {%8,%9}, {%0,%1,%2,%3};"
        : "+f"(d[0]), "+f"(d[1]), "+f"(d[2]), "+f"(d[3])
        : "r"(a[0]), "r"(a[1]), "r"(a[2]), "r"(a[3]), "r"(b[0]), "r"(b[1]));
}

__device__ __forceinline__ void ldsm_x4(unsigned& r0, unsigned& r1,
                                        unsigned& r2, unsigned& r3, unsigned addr) {
    asm volatile("ldmatrix.sync.aligned.m8n8.x4.shared.b16 {%0,%1,%2,%3}, [%4];"
                 : "=r"(r0), "=r"(r1), "=r"(r2), "=r"(r3) : "r"(addr));
}

__global__ __launch_bounds__(256, 1)
void layer_fused_kernel(const __half* __restrict__ in,
                        const __half* __restrict__ w1,   // [c][k]
                        const float* __restrict__ b1,
                        const __half* __restrict__ w2,   // [c][k]
                        const float* __restrict__ b2,
                        __half* __restrict__ outh,
                        float* __restrict__ outf,
                        int nrows) {
    extern __shared__ __half smh[];
    __half* Ws1 = smh;                        // [128][WSTR]
    __half* Ws2 = smh + 128 * WSTR;           // [128][WSTR]
    __half* Xs0 = smh + 2 * 128 * WSTR;       // [128][XSTR]
    __half* Xs1 = Xs0 + TR * XSTR;
    float*  Bs1 = (float*)(Xs1 + TR * XSTR);  // [128]
    float*  Bs2 = Bs1 + 128;                  // [128]

    int tid = threadIdx.x;

    PDL_TRIGGER();
    // Preamble (safe pre-wait: g_wh written by prep, which gates the cascade;
    // biases are harness inputs)
    for (int i = tid; i < 128 * 16; i += 256) {
        int c = i >> 4, seg = i & 15;
        *(uint4*)(Ws1 + c * WSTR + seg * 8) = __ldg((const uint4*)w1 + i);
        *(uint4*)(Ws2 + c * WSTR + seg * 8) = __ldg((const uint4*)w2 + i);
    }
    if (tid < 128) {
        Bs1[tid] = __ldg(b1 + tid);
        Bs2[tid] = __ldg(b2 + tid);
    }
    PDL_WAIT();   // now `in` (gather output) is ready

    int warp = tid >> 5, lane = tid & 31;
    int gi = lane >> 2, ti = lane & 3;
    int mbase = warp * 16;

    int a_row = mbase + (lane & 7) + (((lane >> 3) & 1) << 3);
    int a_koff = (lane >> 4) << 3;
    int b_row = (lane & 7) + ((lane >> 4) << 3);
    int b_koff = ((lane >> 3) & 1) << 3;

    unsigned ws1_base = (unsigned)__cvta_generic_to_shared(Ws1);
    unsigned ws2_base = (unsigned)__cvta_generic_to_shared(Ws2);
    unsigned xs0_base = (unsigned)__cvta_generic_to_shared(Xs0);
    unsigned xs1_base = (unsigned)__cvta_generic_to_shared(Xs1);
    unsigned b_off = (b_row * WSTR + b_koff) * 2;
    unsigned a_off = (a_row * XSTR + a_koff) * 2;

    int ntiles = (nrows + TR - 1) / TR;
    int stride = gridDim.x;

    uint4 reg[8];

    // prologue: tile blockIdx.x -> Xs0
    {
        long long r0 = (long long)blockIdx.x * TR;
#pragma unroll
        for (int p = 0; p < 8; p++) {
            int idx = tid + 256 * p;
            long long gr = r0 + (idx >> 4);
            reg[p] = (gr < nrows) ? __ldg((const uint4*)in + gr * 16 + (idx & 15))
                                  : make_uint4(0, 0, 0, 0);
        }
#pragma unroll
        for (int p = 0; p < 8; p++) {
            int idx = tid + 256 * p;
            *(uint4*)(Xs0 + (idx >> 4) * XSTR + (idx & 15) * 8) = reg[p];
        }
    }
    __syncthreads();

    unsigned xbase[2] = {xs0_base, xs1_base};
    __half* bufs[2] = {Xs0, Xs1};
    int buf = 0;

    for (int tt = blockIdx.x; tt < ntiles; tt += stride) {
        int nxt = tt + stride;
        if (nxt < ntiles) {
            long long r0 = (long long)nxt * TR;
#pragma unroll
            for (int p = 0; p < 8; p++) {
                int idx = tid + 256 * p;
                long long gr = r0 + (idx >> 4);
                reg[p] = (gr < nrows) ? __ldg((const uint4*)in + gr * 16 + (idx & 15))
                                      : make_uint4(0, 0, 0, 0);
            }
        }

        unsigned xs = xbase[buf];

        // ---- MMA1: T[16 rows][128 cols] ----
        float acc1[16][4];
#pragma unroll
        for (int j = 0; j < 16; j++)
#pragma unroll
            for (int q = 0; q < 4; q++) acc1[j][q] = 0.f;

#pragma unroll
        for (int kk = 0; kk < 8; kk++) {
            int k0 = kk * 16;
            unsigned a[4];
            ldsm_x4(a[0], a[1], a[2], a[3], xs + a_off + k0 * 2);
#pragma unroll
            for (int j = 0; j < 16; j += 2) {
                unsigned r0, r1, r2, r3;
                ldsm_x4(r0, r1, r2, r3, ws1_base + b_off + (j * 8 * WSTR + k0) * 2);
                unsigned bj0[2] = {r0, r1};
                unsigned bj1[2] = {r2, r3};
                mma_16x8x16(acc1[j], a, bj0);
                mma_16x8x16(acc1[j + 1], a, bj1);
            }
        }

        // ---- bias1 + relu + convert: C-frag -> A-frag ----
        unsigned af[16][2];
#pragma unroll
        for (int j = 0; j < 16; j++) {
            int c0 = j * 8 + 2 * ti;
            float bx = Bs1[c0], by = Bs1[c0 + 1];
            float v0 = fmaxf(acc1[j][0] + bx, 0.f);
            float v1 = fmaxf(acc1[j][1] + by, 0.f);
            float v2 = fmaxf(acc1[j][2] + bx, 0.f);
            float v3 = fmaxf(acc1[j][3] + by, 0.f);
            __half2 lo = __floats2half2_rn(v0, v1);
            __half2 hi = __floats2half2_rn(v2, v3);
            af[j][0] = *(unsigned*)&lo;
            af[j][1] = *(unsigned*)&hi;
        }

        // ---- MMA2 ----
        float acc2[16][4];
#pragma unroll
        for (int j = 0; j < 16; j++)
#pragma unroll
            for (int q = 0; q < 4; q++) acc2[j][q] = 0.f;

#pragma unroll
        for (int kk = 0; kk < 8; kk++) {
            int k0 = kk * 16;
            unsigned a[4] = {af[2 * kk][0], af[2 * kk][1],
                             af[2 * kk + 1][0], af[2 * kk + 1][1]};
#pragma unroll
            for (int j = 0; j < 16; j += 2) {
                unsigned r0, r1, r2, r3;
                ldsm_x4(r0, r1, r2, r3, ws2_base + b_off + (j * 8 * WSTR + k0) * 2);
                unsigned bj0[2] = {r0, r1};
                unsigned bj1[2] = {r2, r3};
                mma_16x8x16(acc2[j], a, bj0);
                mma_16x8x16(acc2[j + 1], a, bj1);
            }
        }

        // ---- epilogue ----
        long long row0 = (long long)tt * TR + mbase + gi;
#pragma unroll
        for (int j = 0; j < 16; j++) {
            int c0 = j * 8 + 2 * ti;
            float bx = Bs2[c0], by = Bs2[c0 + 1];
            float v0 = acc2[j][0] + bx;
            float v1 = acc2[j][1] + by;
            float v2 = acc2[j][2] + bx;
            float v3 = acc2[j][3] + by;
            if (outf) {
                if (row0 < nrows)
                    *(float2*)(outf + row0 * D + c0) = make_float2(v0, v1);
                if (row0 + 8 < nrows)
                    *(float2*)(outf + (row0 + 8) * D + c0) = make_float2(v2, v3);
            } else {
                if (row0 < nrows)
                    *(__half2*)(outh + row0 * D + c0) = __floats2half2_rn(v0, v1);
                if (row0 + 8 < nrows)
                    *(__half2*)(outh + (row0 + 8) * D + c0) = __floats2half2_rn(v2, v3);
            }
        }

        if (nxt < ntiles) {
#pragma unroll
            for (int p = 0; p < 8; p++) {
                int idx = tid + 256 * p;
                *(uint4*)(bufs[buf ^ 1] + (idx >> 4) * XSTR + (idx & 15) * 8) = reg[p];
            }
            __syncthreads();
            buf ^= 1;
        }
    }
}

// ---------------------------------------------------------------------------
template <typename... Args>
static void pdl_launch(void (*kern)(Args...), int grid, int block, size_t smem,
                       Args... args) {
    cudaLaunchAttribute attr;
    attr.id = cudaLaunchAttributeProgrammaticStreamSerialization;
    attr.val.programmaticStreamSerializationAllowed = 1;
    cudaLaunchConfig_t cfg = {};
    cfg.gridDim = dim3((unsigned)grid);
    cfg.blockDim = dim3((unsigned)block);
    cfg.dynamicSmemBytes = smem;
    cfg.stream = 0;
    cfg.attrs = &attr;
    cfg.numAttrs = 1;
    cudaLaunchKernelEx(&cfg, kern, args...);
}

extern "C" void kernel_launch(void* const* d_in, const int* in_sizes, int n_in,
                              void* d_out, int out_size) {
    const float* x   = (const float*)d_in[0];
    const int*   ei  = (const int*)d_in[1];
    const float* w0a = (const float*)d_in[2];
    const float* b0a = (const float*)d_in[3];
    const float* w0b = (const float*)d_in[4];
    const float* b0b = (const float*)d_in[5];
    const float* w1a = (const float*)d_in[6];
    const float* b1a = (const float*)d_in[7];
    const float* w1b = (const float*)d_in[8];
    const float* b1b = (const float*)d_in[9];

    int N = in_sizes[0] / D;
    int E = in_sizes[1] / 2;

    __half *p_xh, *p_hh, *p_oh, *p_wh;
    cudaGetSymbolAddress((void**)&p_xh, g_xh);
    cudaGetSymbolAddress((void**)&p_hh, g_hh);
    cudaGetSymbolAddress((void**)&p_oh, g_oh);
    cudaGetSymbolAddress((void**)&p_wh, g_wh);

    int nsm = 148;
    cudaDeviceGetAttribute(&nsm, cudaDevAttrMultiProcessorCount, 0);

    const size_t smem = (2 * 128 * WSTR + 2 * TR * XSTR) * sizeof(__half)
                      + 256 * sizeof(float);
    cudaFuncSetAttribute(layer_fused_kernel, cudaFuncAttributeMaxDynamicSharedMemorySize,
                         (int)smem);

    int nb = (N + 1023) / 1024;
    int gatherBlocks = (N + 7) / 8;
    int n4 = N * (D / 4);
    int e4 = (E + 3) / 4;
    int prepTotal = 4 * D * D + n4 + N;

    prep_kernel<<<(prepTotal + 255) / 256, 256>>>(x, w0a, w0b, w1a, w1b, n4, N);
    hist_kernel<<<(e4 + 255) / 256, 256>>>(ei, E);

    pdl_launch(scan1_kernel, nb, 1024, 0, N);
    pdl_launch(scan23_kernel, nb, 1024, 0, N, E);
    pdl_launch(fill_kernel, (e4 + 255) / 256, 256, (size_t)0, ei, E);

    // ---- Layer 1 ----
    pdl_launch(gather_h_kernel, gatherBlocks, 256, (size_t)0,
               (const __half*)p_xh, (__half*)p_hh, N);
    pdl_launch(layer_fused_kernel, nsm, 256, smem,
               (const __half*)p_hh, (const __half*)(p_wh + 0 * D * D), b0a,
               (const __half*)(p_wh + 1 * D * D), b0b,
               (__half*)p_oh, (float*)nullptr, N);

    // ---- Layer 2 ----
    pdl_launch(gather_h_kernel, gatherBlocks, 256, (size_t)0,
               (const __half*)p_oh, (__half*)p_hh, N);
    pdl_launch(layer_fused_kernel, nsm, 256, smem,
               (const __half*)p_hh, (const __half*)(p_wh + 2 * D * D), b1a,
               (const __half*)(p_wh + 3 * D * D), b1b,
               (__half*)nullptr, (float*)d_out, N);
}

// round 13
// speedup vs baseline: 1.5064x; 1.0154x over previous
#include <cuda_runtime.h>
#include <cuda_fp16.h>
#include <cstdint>

#define D 128
#define MAXN 100000
#define MAXE 1600000

#define PDL_TRIGGER() asm volatile("griddepcontrol.launch_dependents;" ::: "memory")
#define PDL_WAIT()    asm volatile("griddepcontrol.wait;" ::: "memory")

__device__ __align__(16) __half g_xh[(size_t)MAXN * D];
__device__ __align__(16) __half g_hh[(size_t)MAXN * D];
__device__ __align__(16) __half g_oh[(size_t)MAXN * D];
__device__ __align__(16) __half g_wh[4 * D * D];   // weights [c][k] fp16
__device__ int g_deg[MAXN];
__device__ unsigned g_state[128];                  // lookback: flag(2b)<<30 | value
__device__ int g_rowptr[MAXN + 1];
__device__ int g_rank[MAXE];
__device__ int g_elist[MAXE];

// ---------------------------------------------------------------------------
// prep: convert weights + x to fp16, zero deg + lookback state. Plain-launched
// first kernel; full completion gates everything downstream.
__global__ void prep_kernel(const float* __restrict__ x,
                            const float* __restrict__ w0,
                            const float* __restrict__ w1,
                            const float* __restrict__ w2,
                            const float* __restrict__ w3,
                            int n4, int n) {
    int i = blockIdx.x * blockDim.x + threadIdx.x;
    if (i < 4 * D * D) {
        int widx = i >> 14;
        const float* w = (widx == 0) ? w0 : (widx == 1) ? w1 : (widx == 2) ? w2 : w3;
        g_wh[i] = __float2half(w[i & 16383]);
    }
    int j = i - 4 * D * D;
    if (j >= 0 && j < n4) {
        float4 v = __ldg((const float4*)x + j);
        __half2 h0 = __floats2half2_rn(v.x, v.y);
        __half2 h1 = __floats2half2_rn(v.z, v.w);
        uint2 u;
        u.x = *(unsigned*)&h0;
        u.y = *(unsigned*)&h1;
        ((uint2*)g_xh)[j] = u;
    }
    int k = j - n4;
    if (k >= 0 && k < n) g_deg[k] = 0;
    int k2 = k - n;
    if (k2 >= 0 && k2 < 128) g_state[k2] = 0;
}

// ---------------------------------------------------------------------------
// hist: per-dst degree count; atomicAdd's return value IS the edge's rank
// within its node — saved for the atomic-free fill.
__global__ void hist_kernel(const int* __restrict__ ei, int E) {
    int t = blockIdx.x * blockDim.x + threadIdx.x;
    int base = t * 4;
    if (base + 4 <= E) {
        int4 d = __ldg((const int4*)(ei + E) + t);
        int4 r;
        r.x = atomicAdd(&g_deg[d.x], 1);
        r.y = atomicAdd(&g_deg[d.y], 1);
        r.z = atomicAdd(&g_deg[d.z], 1);
        r.w = atomicAdd(&g_deg[d.w], 1);
        ((int4*)g_rank)[t] = r;
    } else {
        for (int e = base; e < E; e++)
            g_rank[e] = atomicAdd(&g_deg[__ldg(ei + E + e)], 1);
    }
    PDL_TRIGGER();   // after all writes — spec-correct
}

// ---------------------------------------------------------------------------
// Fused single-pass scan (decoupled lookback): rowptr = exclusive scan of deg.
// Flag+value packed in one 32-bit word -> no fences needed. 98 blocks, all
// co-resident on 148 SMs -> no deadlock.
__global__ void scan_fused_kernel(int n, int E) {
    PDL_WAIT();
    __shared__ int wsum[32];
    __shared__ int sPre;
    int t = threadIdx.x, b = blockIdx.x;
    int i = b * 1024 + t;
    int lane = t & 31, warp = t >> 5;
    int v = (i < n) ? g_deg[i] : 0;
    int s = v;
#pragma unroll
    for (int off = 1; off < 32; off <<= 1) {
        int u = __shfl_up_sync(0xffffffffu, s, off);
        if (lane >= off) s += u;
    }
    if (lane == 31) wsum[warp] = s;
    __syncthreads();
    if (warp == 0) {
        int ws = wsum[lane];
#pragma unroll
        for (int off = 1; off < 32; off <<= 1) {
            int u = __shfl_up_sync(0xffffffffu, ws, off);
            if (lane >= off) ws += u;
        }
        wsum[lane] = ws;
    }
    __syncthreads();
    int incl = s + (warp > 0 ? wsum[warp - 1] : 0);
    int blockAgg = wsum[31];

    if (t == 0) {
        unsigned flag = (b == 0) ? 2u : 1u;
        atomicExch(&g_state[b], (flag << 30) | (unsigned)blockAgg);
        if (b == 0) sPre = 0;
    }
    // warp-parallel lookback
    if (warp == 0 && b > 0) {
        int prefix = 0;
        int j = b - 1;
        while (true) {
            int idx = j - lane;
            unsigned st;
            do {
                st = (idx >= 0) ? *(volatile unsigned*)&g_state[idx] : (2u << 30);
            } while (__any_sync(0xffffffffu, (st >> 30) == 0));
            unsigned pm = __ballot_sync(0xffffffffu, idx >= 0 && (st >> 30) == 2u);
            if (pm) {
                int stop = __ffs(pm) - 1;   // lowest lane = most recent flag-2
                int contrib = (lane <= stop && idx >= 0) ? (int)(st & 0x3FFFFFFF) : 0;
#pragma unroll
                for (int off = 16; off; off >>= 1)
                    contrib += __shfl_down_sync(0xffffffffu, contrib, off);
                prefix += __shfl_sync(0xffffffffu, contrib, 0);
                break;
            } else {
                int contrib = (idx >= 0) ? (int)(st & 0x3FFFFFFF) : 0;
#pragma unroll
                for (int off = 16; off; off >>= 1)
                    contrib += __shfl_down_sync(0xffffffffu, contrib, off);
                prefix += __shfl_sync(0xffffffffu, contrib, 0);
                j -= 32;
            }
        }
        if (lane == 0) {
            sPre = prefix;
            atomicExch(&g_state[b], (2u << 30) | (unsigned)(prefix + blockAgg));
        }
    }
    __syncthreads();
    int excl = sPre + incl - v;
    if (i < n) g_rowptr[i] = excl;
    if (i == 0) g_rowptr[n] = E;
    PDL_TRIGGER();
}

// ---------------------------------------------------------------------------
// fill: atomic-free — pos = rowptr[dst] + rank.
__global__ void fill_kernel(const int* __restrict__ ei, int E) {
    PDL_WAIT();
    int t = blockIdx.x * blockDim.x + threadIdx.x;
    int base = t * 4;
    if (base + 4 <= E) {
        int4 s = __ldg((const int4*)ei + t);
        int4 d = __ldg((const int4*)(ei + E) + t);
        int4 r = ((const int4*)g_rank)[t];
        g_elist[__ldg(g_rowptr + d.x) + r.x] = s.x;
        g_elist[__ldg(g_rowptr + d.y) + r.y] = s.y;
        g_elist[__ldg(g_rowptr + d.z) + r.z] = s.z;
        g_elist[__ldg(g_rowptr + d.w) + r.w] = s.w;
    } else {
        for (int e = base; e < E; e++) {
            int s = __ldg(ei + e);
            int d = __ldg(ei + E + e);
            g_elist[__ldg(g_rowptr + d) + g_rank[e]] = s;
        }
    }
    PDL_TRIGGER();
}

// ---------------------------------------------------------------------------
// Gather: h[n] = x[n] + sum_{s in N(n)} x[s].  One warp per node (standalone —
// fusing into the MLP regressed twice; scheduler load-balancing is load-bearing).
__device__ __forceinline__ void acc_add(float4& a, uint2 u) {
    float2 f0 = __half22float2(*(__half2*)&u.x);
    float2 f1 = __half22float2(*(__half2*)&u.y);
    a.x += f0.x; a.y += f0.y; a.z += f1.x; a.w += f1.y;
}

__global__ void gather_h_kernel(const __half* __restrict__ xin,
                                __half* __restrict__ hout, int N) {
    PDL_WAIT();
    int w = (int)((blockIdx.x * (unsigned)blockDim.x + threadIdx.x) >> 5);
    if (w >= N) return;
    int lane = threadIdx.x & 31;
    const uint2* x2 = (const uint2*)xin;
    float4 acc = make_float4(0.f, 0.f, 0.f, 0.f);
    acc_add(acc, __ldg(x2 + (long long)w * 32 + lane));
    int beg = __ldg(g_rowptr + w);
    int end = __ldg(g_rowptr + w + 1);
    int i = beg;
    for (; i + 4 <= end; i += 4) {
        int s0 = __ldg(g_elist + i);
        int s1 = __ldg(g_elist + i + 1);
        int s2 = __ldg(g_elist + i + 2);
        int s3 = __ldg(g_elist + i + 3);
        uint2 v0 = __ldg(x2 + (long long)s0 * 32 + lane);
        uint2 v1 = __ldg(x2 + (long long)s1 * 32 + lane);
        uint2 v2 = __ldg(x2 + (long long)s2 * 32 + lane);
        uint2 v3 = __ldg(x2 + (long long)s3 * 32 + lane);
        acc_add(acc, v0); acc_add(acc, v1); acc_add(acc, v2); acc_add(acc, v3);
    }
    for (; i < end; i++) {
        int s0 = __ldg(g_elist + i);
        acc_add(acc, __ldg(x2 + (long long)s0 * 32 + lane));
    }
    __half2 h0 = __floats2half2_rn(acc.x, acc.y);
    __half2 h1 = __floats2half2_rn(acc.z, acc.w);
    uint2 u;
    u.x = *(unsigned*)&h0;
    u.y = *(unsigned*)&h1;
    ((uint2*)hout)[(long long)w * 32 + lane] = u;
    PDL_TRIGGER();   // after this warp's store
}

// ---------------------------------------------------------------------------
// Fused layer (register-resident): out = relu(X@W1^T+b1)@W2^T+b2.
// Persistent, 148 blocks, double-buffered X tiles, ldmatrix fragment loads.
// PDL: W/bias preamble BEFORE the wait (safe: g_wh written by plain-serialized
// prep); trigger at the END (after all output stores).
#define XSTR 136
#define WSTR 136
#define TR 128

__device__ __forceinline__ void mma_16x8x16(float* d, const unsigned* a, const unsigned* b) {
    asm volatile(
        "mma.sync.aligned.m16n8k16.row.col.f32.f16.f16.f32 "
        "{%0,%1,%2,%3}, {%4,%5,%6,%7}, {%8,%9}, {%0,%1,%2,%3};"
        : "+f"(d[0]), "+f"(d[1]), "+f"(d[2]), "+f"(d[3])
        : "r"(a[0]), "r"(a[1]), "r"(a[2]), "r"(a[3]), "r"(b[0]), "r"(b[1]));
}

__device__ __forceinline__ void ldsm_x4(unsigned& r0, unsigned& r1,
                                        unsigned& r2, unsigned& r3, unsigned addr) {
    asm volatile("ldmatrix.sync.aligned.m8n8.x4.shared.b16 {%0,%1,%2,%3}, [%4];"
                 : "=r"(r0), "=r"(r1), "=r"(r2), "=r"(r3) : "r"(addr));
}

__global__ __launch_bounds__(256, 1)
void layer_fused_kernel(const __half* __restrict__ in,
                        const __half* __restrict__ w1,   // [c][k]
                        const float* __restrict__ b1,
                        const __half* __restrict__ w2,   // [c][k]
                        const float* __restrict__ b2,
                        __half* __restrict__ outh,
                        float* __restrict__ outf,
                        int nrows) {
    extern __shared__ __half smh[];
    __half* Ws1 = smh;                        // [128][WSTR]
    __half* Ws2 = smh + 128 * WSTR;           // [128][WSTR]
    __half* Xs0 = smh + 2 * 128 * WSTR;       // [128][XSTR]
    __half* Xs1 = Xs0 + TR * XSTR;
    float*  Bs1 = (float*)(Xs1 + TR * XSTR);  // [128]
    float*  Bs2 = Bs1 + 128;                  // [128]

    int tid = threadIdx.x;

    // Preamble before wait (overlaps predecessor tail)
    for (int i = tid; i < 128 * 16; i += 256) {
        int c = i >> 4, seg = i & 15;
        *(uint4*)(Ws1 + c * WSTR + seg * 8) = __ldg((const uint4*)w1 + i);
        *(uint4*)(Ws2 + c * WSTR + seg * 8) = __ldg((const uint4*)w2 + i);
    }
    if (tid < 128) {
        Bs1[tid] = __ldg(b1 + tid);
        Bs2[tid] = __ldg(b2 + tid);
    }
    PDL_WAIT();   // now `in` (gather output) is ready

    int warp = tid >> 5, lane = tid & 31;
    int gi = lane >> 2, ti = lane & 3;
    int mbase = warp * 16;

    int a_row = mbase + (lane & 7) + (((lane >> 3) & 1) << 3);
    int a_koff = (lane >> 4) << 3;
    int b_row = (lane & 7) + ((lane >> 4) << 3);
    int b_koff = ((lane >> 3) & 1) << 3;

    unsigned ws1_base = (unsigned)__cvta_generic_to_shared(Ws1);
    unsigned ws2_base = (unsigned)__cvta_generic_to_shared(Ws2);
    unsigned xs0_base = (unsigned)__cvta_generic_to_shared(Xs0);
    unsigned xs1_base = (unsigned)__cvta_generic_to_shared(Xs1);
    unsigned b_off = (b_row * WSTR + b_koff) * 2;
    unsigned a_off = (a_row * XSTR + a_koff) * 2;

    int ntiles = (nrows + TR - 1) / TR;
    int stride = gridDim.x;

    uint4 reg[8];

    // prologue: tile blockIdx.x -> Xs0
    {
        long long r0 = (long long)blockIdx.x * TR;
#pragma unroll
        for (int p = 0; p < 8; p++) {
            int idx = tid + 256 * p;
            long long gr = r0 + (idx >> 4);
            reg[p] = (gr < nrows) ? __ldg((const uint4*)in + gr * 16 + (idx & 15))
                                  : make_uint4(0, 0, 0, 0);
        }
#pragma unroll
        for (int p = 0; p < 8; p++) {
            int idx = tid + 256 * p;
            *(uint4*)(Xs0 + (idx >> 4) * XSTR + (idx & 15) * 8) = reg[p];
        }
    }
    __syncthreads();

    unsigned xbase[2] = {xs0_base, xs1_base};
    __half* bufs[2] = {Xs0, Xs1};
    int buf = 0;

    for (int tt = blockIdx.x; tt < ntiles; tt += stride) {
        int nxt = tt + stride;
        if (nxt < ntiles) {
            long long r0 = (long long)nxt * TR;
#pragma unroll
            for (int p = 0; p < 8; p++) {
                int idx = tid + 256 * p;
                long long gr = r0 + (idx >> 4);
                reg[p] = (gr < nrows) ? __ldg((const uint4*)in + gr * 16 + (idx & 15))
                                      : make_uint4(0, 0, 0, 0);
            }
        }

        unsigned xs = xbase[buf];

        // ---- MMA1: T[16 rows][128 cols] ----
        float acc1[16][4];
#pragma unroll
        for (int j = 0; j < 16; j++)
#pragma unroll
            for (int q = 0; q < 4; q++) acc1[j][q] = 0.f;

#pragma unroll
        for (int kk = 0; kk < 8; kk++) {
            int k0 = kk * 16;
            unsigned a[4];
            ldsm_x4(a[0], a[1], a[2], a[3], xs + a_off + k0 * 2);
#pragma unroll
            for (int j = 0; j < 16; j += 2) {
                unsigned r0, r1, r2, r3;
                ldsm_x4(r0, r1, r2, r3, ws1_base + b_off + (j * 8 * WSTR + k0) * 2);
                unsigned bj0[2] = {r0, r1};
                unsigned bj1[2] = {r2, r3};
                mma_16x8x16(acc1[j], a, bj0);
                mma_16x8x16(acc1[j + 1], a, bj1);
            }
        }

        // ---- bias1 + relu + convert: C-frag -> A-frag ----
        unsigned af[16][2];
#pragma unroll
        for (int j = 0; j < 16; j++) {
            int c0 = j * 8 + 2 * ti;
            float bx = Bs1[c0], by = Bs1[c0 + 1];
            float v0 = fmaxf(acc1[j][0] + bx, 0.f);
            float v1 = fmaxf(acc1[j][1] + by, 0.f);
            float v2 = fmaxf(acc1[j][2] + bx, 0.f);
            float v3 = fmaxf(acc1[j][3] + by, 0.f);
            __half2 lo = __floats2half2_rn(v0, v1);
            __half2 hi = __floats2half2_rn(v2, v3);
            af[j][0] = *(unsigned*)&lo;
            af[j][1] = *(unsigned*)&hi;
        }

        // ---- MMA2 ----
        float acc2[16][4];
#pragma unroll
        for (int j = 0; j < 16; j++)
#pragma unroll
            for (int q = 0; q < 4; q++) acc2[j][q] = 0.f;

#pragma unroll
        for (int kk = 0; kk < 8; kk++) {
            int k0 = kk * 16;
            unsigned a[4] = {af[2 * kk][0], af[2 * kk][1],
                             af[2 * kk + 1][0], af[2 * kk + 1][1]};
#pragma unroll
            for (int j = 0; j < 16; j += 2) {
                unsigned r0, r1, r2, r3;
                ldsm_x4(r0, r1, r2, r3, ws2_base + b_off + (j * 8 * WSTR + k0) * 2);
                unsigned bj0[2] = {r0, r1};
                unsigned bj1[2] = {r2, r3};
                mma_16x8x16(acc2[j], a, bj0);
                mma_16x8x16(acc2[j + 1], a, bj1);
            }
        }

        // ---- epilogue ----
        long long row0 = (long long)tt * TR + mbase + gi;
#pragma unroll
        for (int j = 0; j < 16; j++) {
            int c0 = j * 8 + 2 * ti;
            float bx = Bs2[c0], by = Bs2[c0 + 1];
            float v0 = acc2[j][0] + bx;
            float v1 = acc2[j][1] + by;
            float v2 = acc2[j][2] + bx;
            float v3 = acc2[j][3] + by;
            if (outf) {
                if (row0 < nrows)
                    *(float2*)(outf + row0 * D + c0) = make_float2(v0, v1);
                if (row0 + 8 < nrows)
                    *(float2*)(outf + (row0 + 8) * D + c0) = make_float2(v2, v3);
            } else {
                if (row0 < nrows)
                    *(__half2*)(outh + row0 * D + c0) = __floats2half2_rn(v0, v1);
                if (row0 + 8 < nrows)
                    *(__half2*)(outh + (row0 + 8) * D + c0) = __floats2half2_rn(v2, v3);
            }
        }

        if (nxt < ntiles) {
#pragma unroll
            for (int p = 0; p < 8; p++) {
                int idx = tid + 256 * p;
                *(uint4*)(bufs[buf ^ 1] + (idx >> 4) * XSTR + (idx & 15) * 8) = reg[p];
            }
            __syncthreads();
            buf ^= 1;
        }
    }
    PDL_TRIGGER();   // after all output stores
}

// ---------------------------------------------------------------------------
template <typename... Args>
static void pdl_launch(void (*kern)(Args...), int grid, int block, size_t smem,
                       Args... args) {
    cudaLaunchAttribute attr;
    attr.id = cudaLaunchAttributeProgrammaticStreamSerialization;
    attr.val.programmaticStreamSerializationAllowed = 1;
    cudaLaunchConfig_t cfg = {};
    cfg.gridDim = dim3((unsigned)grid);
    cfg.blockDim = dim3((unsigned)block);
    cfg.dynamicSmemBytes = smem;
    cfg.stream = 0;
    cfg.attrs = &attr;
    cfg.numAttrs = 1;
    cudaLaunchKernelEx(&cfg, kern, args...);
}

extern "C" void kernel_launch(void* const* d_in, const int* in_sizes, int n_in,
                              void* d_out, int out_size) {
    const float* x   = (const float*)d_in[0];
    const int*   ei  = (const int*)d_in[1];
    const float* w0a = (const float*)d_in[2];
    const float* b0a = (const float*)d_in[3];
    const float* w0b = (const float*)d_in[4];
    const float* b0b = (const float*)d_in[5];
    const float* w1a = (const float*)d_in[6];
    const float* b1a = (const float*)d_in[7];
    const float* w1b = (const float*)d_in[8];
    const float* b1b = (const float*)d_in[9];

    int N = in_sizes[0] / D;
    int E = in_sizes[1] / 2;

    __half *p_xh, *p_hh, *p_oh, *p_wh;
    cudaGetSymbolAddress((void**)&p_xh, g_xh);
    cudaGetSymbolAddress((void**)&p_hh, g_hh);
    cudaGetSymbolAddress((void**)&p_oh, g_oh);
    cudaGetSymbolAddress((void**)&p_wh, g_wh);

    int nsm = 148;
    cudaDeviceGetAttribute(&nsm, cudaDevAttrMultiProcessorCount, 0);

    const size_t smem = (2 * 128 * WSTR + 2 * TR * XSTR) * sizeof(__half)
                      + 256 * sizeof(float);
    cudaFuncSetAttribute(layer_fused_kernel, cudaFuncAttributeMaxDynamicSharedMemorySize,
                         (int)smem);

    int nb = (N + 1023) / 1024;
    int gatherBlocks = (N + 7) / 8;
    int n4 = N * (D / 4);
    int e4 = (E + 3) / 4;
    int prepTotal = 4 * D * D + n4 + N + 128;

    prep_kernel<<<(prepTotal + 255) / 256, 256>>>(x, w0a, w0b, w1a, w1b, n4, N);
    hist_kernel<<<(e4 + 255) / 256, 256>>>(ei, E);

    pdl_launch(scan_fused_kernel, nb, 1024, (size_t)0, N, E);
    pdl_launch(fill_kernel, (e4 + 255) / 256, 256, (size_t)0, ei, E);

    // ---- Layer 1 ----
    pdl_launch(gather_h_kernel, gatherBlocks, 256, (size_t)0,
               (const __half*)p_xh, (__half*)p_hh, N);
    pdl_launch(layer_fused_kernel, nsm, 256, smem,
               (const __half*)p_hh, (const __half*)(p_wh + 0 * D * D), b0a,
               (const __half*)(p_wh + 1 * D * D), b0b,
               (__half*)p_oh, (float*)nullptr, N);

    // ---- Layer 2 ----
    pdl_launch(gather_h_kernel, gatherBlocks, 256, (size_t)0,
               (const __half*)p_oh, (__half*)p_hh, N);
    pdl_launch(layer_fused_kernel, nsm, 256, smem,
               (const __half*)p_hh, (const __half*)(p_wh + 2 * D * D), b1a,
               (const __half*)(p_wh + 3 * D * D), b1b,
               (__half*)nullptr, (float*)d_out, N);
}

// round 15
// speedup vs baseline: 1.5665x; 1.0399x over previous
#include <cuda_runtime.h>
#include <cuda_fp16.h>
#include <cstdint>

#define D 128
#define MAXN 100000
#define MAXE 1600000

#define PDL_TRIGGER() asm volatile("griddepcontrol.launch_dependents;" ::: "memory")
#define PDL_WAIT()    asm volatile("griddepcontrol.wait;" ::: "memory")

__device__ __align__(16) __half g_xh[(size_t)MAXN * D];
__device__ __align__(16) __half g_hh[(size_t)MAXN * D];
__device__ __align__(16) __half g_oh[(size_t)MAXN * D];
__device__ __align__(16) __half g_wh[4 * D * D];   // weights [c][k] fp16
__device__ int g_deg[MAXN];
__device__ unsigned g_state[128];                  // lookback: flag(2b)<<30 | value
__device__ int g_rowptr[MAXN + 1];
__device__ int g_rank[MAXE];
__device__ int g_elist[MAXE];

// ---------------------------------------------------------------------------
__global__ void prep_kernel(const float* __restrict__ x,
                            const float* __restrict__ w0,
                            const float* __restrict__ w1,
                            const float* __restrict__ w2,
                            const float* __restrict__ w3,
                            int n4, int n) {
    int i = blockIdx.x * blockDim.x + threadIdx.x;
    if (i < 4 * D * D) {
        int widx = i >> 14;
        const float* w = (widx == 0) ? w0 : (widx == 1) ? w1 : (widx == 2) ? w2 : w3;
        g_wh[i] = __float2half(w[i & 16383]);
    }
    int j = i - 4 * D * D;
    if (j >= 0 && j < n4) {
        float4 v = __ldg((const float4*)x + j);
        __half2 h0 = __floats2half2_rn(v.x, v.y);
        __half2 h1 = __floats2half2_rn(v.z, v.w);
        uint2 u;
        u.x = *(unsigned*)&h0;
        u.y = *(unsigned*)&h1;
        ((uint2*)g_xh)[j] = u;
    }
    int k = j - n4;
    if (k >= 0 && k < n) g_deg[k] = 0;
    int k2 = k - n;
    if (k2 >= 0 && k2 < 128) g_state[k2] = 0;
}

// ---------------------------------------------------------------------------
__global__ void hist_kernel(const int* __restrict__ ei, int E) {
    int t = blockIdx.x * blockDim.x + threadIdx.x;
    int base = t * 4;
    if (base + 4 <= E) {
        int4 d = __ldg((const int4*)(ei + E) + t);
        int4 r;
        r.x = atomicAdd(&g_deg[d.x], 1);
        r.y = atomicAdd(&g_deg[d.y], 1);
        r.z = atomicAdd(&g_deg[d.z], 1);
        r.w = atomicAdd(&g_deg[d.w], 1);
        ((int4*)g_rank)[t] = r;
    } else {
        for (int e = base; e < E; e++)
            g_rank[e] = atomicAdd(&g_deg[__ldg(ei + E + e)], 1);
    }
    PDL_TRIGGER();
}

__global__ void scan_fused_kernel(int n, int E) {
    PDL_WAIT();
    __shared__ int wsum[32];
    __shared__ int sPre;
    int t = threadIdx.x, b = blockIdx.x;
    int i = b * 1024 + t;
    int lane = t & 31, warp = t >> 5;
    int v = (i < n) ? g_deg[i] : 0;
    int s = v;
#pragma unroll
    for (int off = 1; off < 32; off <<= 1) {
        int u = __shfl_up_sync(0xffffffffu, s, off);
        if (lane >= off) s += u;
    }
    if (lane == 31) wsum[warp] = s;
    __syncthreads();
    if (warp == 0) {
        int ws = wsum[lane];
#pragma unroll
        for (int off = 1; off < 32; off <<= 1) {
            int u = __shfl_up_sync(0xffffffffu, ws, off);
            if (lane >= off) ws += u;
        }
        wsum[lane] = ws;
    }
    __syncthreads();
    int incl = s + (warp > 0 ? wsum[warp - 1] : 0);
    int blockAgg = wsum[31];

    if (t == 0) {
        unsigned flag = (b == 0) ? 2u : 1u;
        atomicExch(&g_state[b], (flag << 30) | (unsigned)blockAgg);
        if (b == 0) sPre = 0;
    }
    if (warp == 0 && b > 0) {
        int prefix = 0;
        int j = b - 1;
        while (true) {
            int idx = j - lane;
            unsigned st;
            do {
                st = (idx >= 0) ? *(volatile unsigned*)&g_state[idx] : (2u << 30);
            } while (__any_sync(0xffffffffu, (st >> 30) == 0));
            unsigned pm = __ballot_sync(0xffffffffu, idx >= 0 && (st >> 30) == 2u);
            if (pm) {
                int stop = __ffs(pm) - 1;
                int contrib = (lane <= stop && idx >= 0) ? (int)(st & 0x3FFFFFFF) : 0;
#pragma unroll
                for (int off = 16; off; off >>= 1)
                    contrib += __shfl_down_sync(0xffffffffu, contrib, off);
                prefix += __shfl_sync(0xffffffffu, contrib, 0);
                break;
            } else {
                int contrib = (idx >= 0) ? (int)(st & 0x3FFFFFFF) : 0;
#pragma unroll
                for (int off = 16; off; off >>= 1)
                    contrib += __shfl_down_sync(0xffffffffu, contrib, off);
                prefix += __shfl_sync(0xffffffffu, contrib, 0);
                j -= 32;
            }
        }
        if (lane == 0) {
            sPre = prefix;
            atomicExch(&g_state[b], (2u << 30) | (unsigned)(prefix + blockAgg));
        }
    }
    __syncthreads();
    int excl = sPre + incl - v;
    if (i < n) g_rowptr[i] = excl;
    if (i == 0) g_rowptr[n] = E;
    PDL_TRIGGER();
}

__global__ void fill_kernel(const int* __restrict__ ei, int E) {
    PDL_WAIT();
    int t = blockIdx.x * blockDim.x + threadIdx.x;
    int base = t * 4;
    if (base + 4 <= E) {
        int4 s = __ldg((const int4*)ei + t);
        int4 d = __ldg((const int4*)(ei + E) + t);
        int4 r = ((const int4*)g_rank)[t];
        g_elist[__ldg(g_rowptr + d.x) + r.x] = s.x;
        g_elist[__ldg(g_rowptr + d.y) + r.y] = s.y;
        g_elist[__ldg(g_rowptr + d.z) + r.z] = s.z;
        g_elist[__ldg(g_rowptr + d.w) + r.w] = s.w;
    } else {
        for (int e = base; e < E; e++) {
            int s = __ldg(ei + e);
            int d = __ldg(ei + E + e);
            g_elist[__ldg(g_rowptr + d) + g_rank[e]] = s;
        }
    }
    PDL_TRIGGER();
}

// ---------------------------------------------------------------------------
// Gather: h[n] = x[n] + sum_{s in N(n)} x[s].
// 16 lanes per node, 2 nodes per warp, uint4 (16B) row loads: same bytes,
// half the LDG instructions per edge. Per-feature add order == elist order
// (bit-identical to the 32-lane version).
__device__ __forceinline__ void acc_add4(float4& a0, float4& a1, uint4 u) {
    float2 f0 = __half22float2(*(__half2*)&u.x);
    float2 f1 = __half22float2(*(__half2*)&u.y);
    float2 f2 = __half22float2(*(__half2*)&u.z);
    float2 f3 = __half22float2(*(__half2*)&u.w);
    a0.x += f0.x; a0.y += f0.y; a0.z += f1.x; a0.w += f1.y;
    a1.x += f2.x; a1.y += f2.y; a1.z += f3.x; a1.w += f3.y;
}

__global__ void gather_h_kernel(const __half* __restrict__ xin,
                                __half* __restrict__ hout, int N) {
    PDL_WAIT();
    int lane = threadIdx.x & 31;
    int sub = lane >> 4;             // half-warp id (0/1)
    int sl = lane & 15;              // lane within half-warp
    long long node = (long long)((blockIdx.x * (unsigned)blockDim.x + threadIdx.x) >> 5) * 2 + sub;
    if (node >= N) return;
    const uint4* x4 = (const uint4*)xin;     // 16 uint4 per row
    float4 a0 = make_float4(0.f, 0.f, 0.f, 0.f);
    float4 a1 = make_float4(0.f, 0.f, 0.f, 0.f);
    acc_add4(a0, a1, __ldg(x4 + node * 16 + sl));
    int beg = __ldg(g_rowptr + node);
    int end = __ldg(g_rowptr + node + 1);
    int i = beg;
    for (; i + 4 <= end; i += 4) {
        int s0 = __ldg(g_elist + i);
        int s1 = __ldg(g_elist + i + 1);
        int s2 = __ldg(g_elist + i + 2);
        int s3 = __ldg(g_elist + i + 3);
        uint4 v0 = __ldg(x4 + (long long)s0 * 16 + sl);
        uint4 v1 = __ldg(x4 + (long long)s1 * 16 + sl);
        uint4 v2 = __ldg(x4 + (long long)s2 * 16 + sl);
        uint4 v3 = __ldg(x4 + (long long)s3 * 16 + sl);
        acc_add4(a0, a1, v0); acc_add4(a0, a1, v1);
        acc_add4(a0, a1, v2); acc_add4(a0, a1, v3);
    }
    for (; i < end; i++) {
        int s0 = __ldg(g_elist + i);
        acc_add4(a0, a1, __ldg(x4 + (long long)s0 * 16 + sl));
    }
    __half2 h0 = __floats2half2_rn(a0.x, a0.y);
    __half2 h1 = __floats2half2_rn(a0.z, a0.w);
    __half2 h2 = __floats2half2_rn(a1.x, a1.y);
    __half2 h3 = __floats2half2_rn(a1.z, a1.w);
    uint4 u;
    u.x = *(unsigned*)&h0;
    u.y = *(unsigned*)&h1;
    u.z = *(unsigned*)&h2;
    u.w = *(unsigned*)&h3;
    ((uint4*)hout)[node * 16 + sl] = u;
    PDL_TRIGGER();
}

// ---------------------------------------------------------------------------
// Fused layer (register-resident): out = relu(X@W1^T+b1)@W2^T+b2.
// Persistent, 148 blocks, double-buffered X tiles, ldmatrix fragment loads.
// PDL: W/bias preamble BEFORE the wait; trigger at the END.
#define XSTR 136
#define WSTR 136
#define TR 128

__device__ __forceinline__ void mma_16x8x16(float* d, const unsigned* a, const unsigned* b) {
    asm volatile(
        "mma.sync.aligned.m16n8k16.row.col.f32.f16.f16.f32 "
        "{%0,%1,%2,%3}, {%4,%5,%6,%7}, {%8,%9}, {%0,%1,%2,%3};"
        : "+f"(d[0]), "+f"(d[1]), "+f"(d[2]), "+f"(d[3])
        : "r"(a[0]), "r"(a[1]), "r"(a[2]), "r"(a[3]), "r"(b[0]), "r"(b[1]));
}

__device__ __forceinline__ void ldsm_x4(unsigned& r0, unsigned& r1,
                                        unsigned& r2, unsigned& r3, unsigned addr) {
    asm volatile("ldmatrix.sync.aligned.m8n8.x4.shared.b16 {%0,%1,%2,%3}, [%4];"
                 : "=r"(r0), "=r"(r1), "=r"(r2), "=r"(r3) : "r"(addr));
}

__global__ __launch_bounds__(256, 1)
void layer_fused_kernel(const __half* __restrict__ in,
                        const __half* __restrict__ w1,   // [c][k]
                        const float* __restrict__ b1,
                        const __half* __restrict__ w2,   // [c][k]
                        const float* __restrict__ b2,
                        __half* __restrict__ outh,
                        float* __restrict__ outf,
                        int nrows) {
    extern __shared__ __half smh[];
    __half* Ws1 = smh;                        // [128][WSTR]
    __half* Ws2 = smh + 128 * WSTR;           // [128][WSTR]
    __half* Xs0 = smh + 2 * 128 * WSTR;       // [128][XSTR]
    __half* Xs1 = Xs0 + TR * XSTR;
    float*  Bs1 = (float*)(Xs1 + TR * XSTR);  // [128]
    float*  Bs2 = Bs1 + 128;                  // [128]

    int tid = threadIdx.x;

    // Preamble before wait (overlaps predecessor tail)
    for (int i = tid; i < 128 * 16; i += 256) {
        int c = i >> 4, seg = i & 15;
        *(uint4*)(Ws1 + c * WSTR + seg * 8) = __ldg((const uint4*)w1 + i);
        *(uint4*)(Ws2 + c * WSTR + seg * 8) = __ldg((const uint4*)w2 + i);
    }
    if (tid < 128) {
        Bs1[tid] = __ldg(b1 + tid);
        Bs2[tid] = __ldg(b2 + tid);
    }
    PDL_WAIT();   // now `in` (gather output) is ready

    int warp = tid >> 5, lane = tid & 31;
    int gi = lane >> 2, ti = lane & 3;
    int mbase = warp * 16;

    int a_row = mbase + (lane & 7) + (((lane >> 3) & 1) << 3);
    int a_koff = (lane >> 4) << 3;
    int b_row = (lane & 7) + ((lane >> 4) << 3);
    int b_koff = ((lane >> 3) & 1) << 3;

    unsigned ws1_base = (unsigned)__cvta_generic_to_shared(Ws1);
    unsigned ws2_base = (unsigned)__cvta_generic_to_shared(Ws2);
    unsigned xs0_base = (unsigned)__cvta_generic_to_shared(Xs0);
    unsigned xs1_base = (unsigned)__cvta_generic_to_shared(Xs1);
    unsigned b_off = (b_row * WSTR + b_koff) * 2;
    unsigned a_off = (a_row * XSTR + a_koff) * 2;

    int ntiles = (nrows + TR - 1) / TR;
    int stride = gridDim.x;

    uint4 reg[8];

    // prologue: tile blockIdx.x -> Xs0
    {
        long long r0 = (long long)blockIdx.x * TR;
#pragma unroll
        for (int p = 0; p < 8; p++) {
            int idx = tid + 256 * p;
            long long gr = r0 + (idx >> 4);
            reg[p] = (gr < nrows) ? __ldg((const uint4*)in + gr * 16 + (idx & 15))
                                  : make_uint4(0, 0, 0, 0);
        }
#pragma unroll
        for (int p = 0; p < 8; p++) {
            int idx = tid + 256 * p;
            *(uint4*)(Xs0 + (idx >> 4) * XSTR + (idx & 15) * 8) = reg[p];
        }
    }
    __syncthreads();

    unsigned xbase[2] = {xs0_base, xs1_base};
    __half* bufs[2] = {Xs0, Xs1};
    int buf = 0;

    for (int tt = blockIdx.x; tt < ntiles; tt += stride) {
        int nxt = tt + stride;
        if (nxt < ntiles) {
            long long r0 = (long long)nxt * TR;
#pragma unroll
            for (int p = 0; p < 8; p++) {
                int idx = tid + 256 * p;
                long long gr = r0 + (idx >> 4);
                reg[p] = (gr < nrows) ? __ldg((const uint4*)in + gr * 16 + (idx & 15))
                                      : make_uint4(0, 0, 0, 0);
            }
        }

        unsigned xs = xbase[buf];

        // ---- MMA1: T[16 rows][128 cols] ----
        float acc1[16][4];
#pragma unroll
        for (int j = 0; j < 16; j++)
#pragma unroll
            for (int q = 0; q < 4; q++) acc1[j][q] = 0.f;

#pragma unroll
        for (int kk = 0; kk < 8; kk++) {
            int k0 = kk * 16;
            unsigned a[4];
            ldsm_x4(a[0], a[1], a[2], a[3], xs + a_off + k0 * 2);
#pragma unroll
            for (int j = 0; j < 16; j += 2) {
                unsigned r0, r1, r2, r3;
                ldsm_x4(r0, r1, r2, r3, ws1_base + b_off + (j * 8 * WSTR + k0) * 2);
                unsigned bj0[2] = {r0, r1};
                unsigned bj1[2] = {r2, r3};
                mma_16x8x16(acc1[j], a, bj0);
                mma_16x8x16(acc1[j + 1], a, bj1);
            }
        }

        // ---- bias1 + relu + convert: C-frag -> A-frag ----
        unsigned af[16][2];
#pragma unroll
        for (int j = 0; j < 16; j++) {
            int c0 = j * 8 + 2 * ti;
            float bx = Bs1[c0], by = Bs1[c0 + 1];
            float v0 = fmaxf(acc1[j][0] + bx, 0.f);
            float v1 = fmaxf(acc1[j][1] + by, 0.f);
            float v2 = fmaxf(acc1[j][2] + bx, 0.f);
            float v3 = fmaxf(acc1[j][3] + by, 0.f);
            __half2 lo = __floats2half2_rn(v0, v1);
            __half2 hi = __floats2half2_rn(v2, v3);
            af[j][0] = *(unsigned*)&lo;
            af[j][1] = *(unsigned*)&hi;
        }

        // ---- MMA2 ----
        float acc2[16][4];
#pragma unroll
        for (int j = 0; j < 16; j++)
#pragma unroll
            for (int q = 0; q < 4; q++) acc2[j][q] = 0.f;

#pragma unroll
        for (int kk = 0; kk < 8; kk++) {
            int k0 = kk * 16;
            unsigned a[4] = {af[2 * kk][0], af[2 * kk][1],
                             af[2 * kk + 1][0], af[2 * kk + 1][1]};
#pragma unroll
            for (int j = 0; j < 16; j += 2) {
                unsigned r0, r1, r2, r3;
                ldsm_x4(r0, r1, r2, r3, ws2_base + b_off + (j * 8 * WSTR + k0) * 2);
                unsigned bj0[2] = {r0, r1};
                unsigned bj1[2] = {r2, r3};
                mma_16x8x16(acc2[j], a, bj0);
                mma_16x8x16(acc2[j + 1], a, bj1);
            }
        }

        // ---- epilogue ----
        long long row0 = (long long)tt * TR + mbase + gi;
#pragma unroll
        for (int j = 0; j < 16; j++) {
            int c0 = j * 8 + 2 * ti;
            float bx = Bs2[c0], by = Bs2[c0 + 1];
            float v0 = acc2[j][0] + bx;
            float v1 = acc2[j][1] + by;
            float v2 = acc2[j][2] + bx;
            float v3 = acc2[j][3] + by;
            if (outf) {
                if (row0 < nrows)
                    *(float2*)(outf + row0 * D + c0) = make_float2(v0, v1);
                if (row0 + 8 < nrows)
                    *(float2*)(outf + (row0 + 8) * D + c0) = make_float2(v2, v3);
            } else {
                if (row0 < nrows)
                    *(__half2*)(outh + row0 * D + c0) = __floats2half2_rn(v0, v1);
                if (row0 + 8 < nrows)
                    *(__half2*)(outh + (row0 + 8) * D + c0) = __floats2half2_rn(v2, v3);
            }
        }

        if (nxt < ntiles) {
#pragma unroll
            for (int p = 0; p < 8; p++) {
                int idx = tid + 256 * p;
                *(uint4*)(bufs[buf ^ 1] + (idx >> 4) * XSTR + (idx & 15) * 8) = reg[p];
            }
            __syncthreads();
            buf ^= 1;
        }
    }
    PDL_TRIGGER();   // after all output stores
}

// ---------------------------------------------------------------------------
template <typename... Args>
static void pdl_launch(void (*kern)(Args...), int grid, int block, size_t smem,
                       Args... args) {
    cudaLaunchAttribute attr;
    attr.id = cudaLaunchAttributeProgrammaticStreamSerialization;
    attr.val.programmaticStreamSerializationAllowed = 1;
    cudaLaunchConfig_t cfg = {};
    cfg.gridDim = dim3((unsigned)grid);
    cfg.blockDim = dim3((unsigned)block);
    cfg.dynamicSmemBytes = smem;
    cfg.stream = 0;
    cfg.attrs = &attr;
    cfg.numAttrs = 1;
    cudaLaunchKernelEx(&cfg, kern, args...);
}

extern "C" void kernel_launch(void* const* d_in, const int* in_sizes, int n_in,
                              void* d_out, int out_size) {
    const float* x   = (const float*)d_in[0];
    const int*   ei  = (const int*)d_in[1];
    const float* w0a = (const float*)d_in[2];
    const float* b0a = (const float*)d_in[3];
    const float* w0b = (const float*)d_in[4];
    const float* b0b = (const float*)d_in[5];
    const float* w1a = (const float*)d_in[6];
    const float* b1a = (const float*)d_in[7];
    const float* w1b = (const float*)d_in[8];
    const float* b1b = (const float*)d_in[9];

    int N = in_sizes[0] / D;
    int E = in_sizes[1] / 2;

    __half *p_xh, *p_hh, *p_oh, *p_wh;
    cudaGetSymbolAddress((void**)&p_xh, g_xh);
    cudaGetSymbolAddress((void**)&p_hh, g_hh);
    cudaGetSymbolAddress((void**)&p_oh, g_oh);
    cudaGetSymbolAddress((void**)&p_wh, g_wh);

    int nsm = 148;
    cudaDeviceGetAttribute(&nsm, cudaDevAttrMultiProcessorCount, 0);

    const size_t smem = (2 * 128 * WSTR + 2 * TR * XSTR) * sizeof(__half)
                      + 256 * sizeof(float);
    cudaFuncSetAttribute(layer_fused_kernel, cudaFuncAttributeMaxDynamicSharedMemorySize,
                         (int)smem);

    int nb = (N + 1023) / 1024;
    int gatherBlocks = (N + 15) / 16;   // 8 warps x 2 nodes per 256-thread block
    int n4 = N * (D / 4);
    int e4 = (E + 3) / 4;
    int prepTotal = 4 * D * D + n4 + N + 128;

    prep_kernel<<<(prepTotal + 255) / 256, 256>>>(x, w0a, w0b, w1a, w1b, n4, N);
    hist_kernel<<<(e4 + 255) / 256, 256>>>(ei, E);

    pdl_launch(scan_fused_kernel, nb, 1024, (size_t)0, N, E);
    pdl_launch(fill_kernel, (e4 + 255) / 256, 256, (size_t)0, ei, E);

    // ---- Layer 1 ----
    pdl_launch(gather_h_kernel, gatherBlocks, 256, (size_t)0,
               (const __half*)p_xh, (__half*)p_hh, N);
    pdl_launch(layer_fused_kernel, nsm, 256, smem,
               (const __half*)p_hh, (const __half*)(p_wh + 0 * D * D), b0a,
               (const __half*)(p_wh + 1 * D * D), b0b,
               (__half*)p_oh, (float*)nullptr, N);

    // ---- Layer 2 ----
    pdl_launch(gather_h_kernel, gatherBlocks, 256, (size_t)0,
               (const __half*)p_oh, (__half*)p_hh, N);
    pdl_launch(layer_fused_kernel, nsm, 256, smem,
               (const __half*)p_hh, (const __half*)(p_wh + 2 * D * D), b1a,
               (const __half*)(p_wh + 3 * D * D), b1b,
               (__half*)nullptr, (float*)d_out, N);
}

// round 16
// speedup vs baseline: 1.5748x; 1.0053x over previous
#include <cuda_runtime.h>
#include <cuda_fp16.h>
#include <cstdint>

#define D 128
#define MAXN 100000
#define MAXE 1600000

#define PDL_TRIGGER() asm volatile("griddepcontrol.launch_dependents;" ::: "memory")
#define PDL_WAIT()    asm volatile("griddepcontrol.wait;" ::: "memory")

__device__ __align__(16) __half g_xh[(size_t)MAXN * D];
__device__ __align__(16) __half g_hh[(size_t)MAXN * D];
__device__ __align__(16) __half g_oh[(size_t)MAXN * D];
__device__ __align__(16) __half g_wh[4 * D * D];   // weights [c][k] fp16
__device__ int g_deg[MAXN];          // ZERO at load; restored to 0 by scan each call
__device__ unsigned g_state[128];    // ZERO at load; restored to 0 by fill each call
__device__ int g_rowptr[MAXN + 1];
__device__ int g_rank[MAXE];
__device__ int g_elist[MAXE];

// ---------------------------------------------------------------------------
// prep+hist merged: weight/x conversion (streaming) overlaps histogram
// (atomics). Legal because g_deg==0 at entry by the self-restoring invariant.
__global__ void prep_hist_kernel(const float* __restrict__ x,
                                 const float* __restrict__ w0,
                                 const float* __restrict__ w1,
                                 const float* __restrict__ w2,
                                 const float* __restrict__ w3,
                                 const int* __restrict__ ei,
                                 int n4, int E, int e4) {
    int i = blockIdx.x * blockDim.x + threadIdx.x;
    if (i < 4 * D * D) {
        int widx = i >> 14;
        const float* w = (widx == 0) ? w0 : (widx == 1) ? w1 : (widx == 2) ? w2 : w3;
        g_wh[i] = __float2half(w[i & 16383]);
    }
    int j = i - 4 * D * D;
    if (j >= 0 && j < n4) {
        float4 v = __ldg((const float4*)x + j);
        __half2 h0 = __floats2half2_rn(v.x, v.y);
        __half2 h1 = __floats2half2_rn(v.z, v.w);
        uint2 u;
        u.x = *(unsigned*)&h0;
        u.y = *(unsigned*)&h1;
        ((uint2*)g_xh)[j] = u;
    }
    // hist role (first e4 threads): 4 edges each
    if (i < e4) {
        int base = i * 4;
        if (base + 4 <= E) {
            int4 d = __ldg((const int4*)(ei + E) + i);
            int4 r;
            r.x = atomicAdd(&g_deg[d.x], 1);
            r.y = atomicAdd(&g_deg[d.y], 1);
            r.z = atomicAdd(&g_deg[d.z], 1);
            r.w = atomicAdd(&g_deg[d.w], 1);
            ((int4*)g_rank)[i] = r;
        } else {
            for (int e = base; e < E; e++)
                g_rank[e] = atomicAdd(&g_deg[__ldg(ei + E + e)], 1);
        }
    }
    PDL_TRIGGER();
}

// ---------------------------------------------------------------------------
// Fused single-pass scan (decoupled lookback). Also RESTORES g_deg to 0 after
// consuming it (self-restoring invariant for the merged prep_hist).
__global__ void scan_fused_kernel(int n, int E) {
    PDL_WAIT();
    __shared__ int wsum[32];
    __shared__ int sPre;
    int t = threadIdx.x, b = blockIdx.x;
    int i = b * 1024 + t;
    int lane = t & 31, warp = t >> 5;
    int v = (i < n) ? g_deg[i] : 0;
    if (i < n) g_deg[i] = 0;          // restore invariant
    int s = v;
#pragma unroll
    for (int off = 1; off < 32; off <<= 1) {
        int u = __shfl_up_sync(0xffffffffu, s, off);
        if (lane >= off) s += u;
    }
    if (lane == 31) wsum[warp] = s;
    __syncthreads();
    if (warp == 0) {
        int ws = wsum[lane];
#pragma unroll
        for (int off = 1; off < 32; off <<= 1) {
            int u = __shfl_up_sync(0xffffffffu, ws, off);
            if (lane >= off) ws += u;
        }
        wsum[lane] = ws;
    }
    __syncthreads();
    int incl = s + (warp > 0 ? wsum[warp - 1] : 0);
    int blockAgg = wsum[31];

    if (t == 0) {
        unsigned flag = (b == 0) ? 2u : 1u;
        atomicExch(&g_state[b], (flag << 30) | (unsigned)blockAgg);
        if (b == 0) sPre = 0;
    }
    if (warp == 0 && b > 0) {
        int prefix = 0;
        int j = b - 1;
        while (true) {
            int idx = j - lane;
            unsigned st;
            do {
                st = (idx >= 0) ? *(volatile unsigned*)&g_state[idx] : (2u << 30);
            } while (__any_sync(0xffffffffu, (st >> 30) == 0));
            unsigned pm = __ballot_sync(0xffffffffu, idx >= 0 && (st >> 30) == 2u);
            if (pm) {
                int stop = __ffs(pm) - 1;
                int contrib = (lane <= stop && idx >= 0) ? (int)(st & 0x3FFFFFFF) : 0;
#pragma unroll
                for (int off = 16; off; off >>= 1)
                    contrib += __shfl_down_sync(0xffffffffu, contrib, off);
                prefix += __shfl_sync(0xffffffffu, contrib, 0);
                break;
            } else {
                int contrib = (idx >= 0) ? (int)(st & 0x3FFFFFFF) : 0;
#pragma unroll
                for (int off = 16; off; off >>= 1)
                    contrib += __shfl_down_sync(0xffffffffu, contrib, off);
                prefix += __shfl_sync(0xffffffffu, contrib, 0);
                j -= 32;
            }
        }
        if (lane == 0) {
            sPre = prefix;
            atomicExch(&g_state[b], (2u << 30) | (unsigned)(prefix + blockAgg));
        }
    }
    __syncthreads();
    int excl = sPre + incl - v;
    if (i < n) g_rowptr[i] = excl;
    if (i == 0) g_rowptr[n] = E;
    PDL_TRIGGER();
}

// ---------------------------------------------------------------------------
// fill: atomic-free; also RESTORES g_state to 0 (scan fully complete by now).
__global__ void fill_kernel(const int* __restrict__ ei, int E) {
    PDL_WAIT();
    int t = blockIdx.x * blockDim.x + threadIdx.x;
    if (t < 128) g_state[t] = 0;      // restore invariant
    int base = t * 4;
    if (base + 4 <= E) {
        int4 s = __ldg((const int4*)ei + t);
        int4 d = __ldg((const int4*)(ei + E) + t);
        int4 r = ((const int4*)g_rank)[t];
        g_elist[__ldg(g_rowptr + d.x) + r.x] = s.x;
        g_elist[__ldg(g_rowptr + d.y) + r.y] = s.y;
        g_elist[__ldg(g_rowptr + d.z) + r.z] = s.z;
        g_elist[__ldg(g_rowptr + d.w) + r.w] = s.w;
    } else {
        for (int e = base; e < E; e++) {
            int s = __ldg(ei + e);
            int d = __ldg(ei + E + e);
            g_elist[__ldg(g_rowptr + d) + g_rank[e]] = s;
        }
    }
    PDL_TRIGGER();
}

// ---------------------------------------------------------------------------
// Gather: h[n] = x[n] + sum_{s in N(n)} x[s].
// 16 lanes per node, 2 nodes per warp, uint4 row loads.
__device__ __forceinline__ void acc_add4(float4& a0, float4& a1, uint4 u) {
    float2 f0 = __half22float2(*(__half2*)&u.x);
    float2 f1 = __half22float2(*(__half2*)&u.y);
    float2 f2 = __half22float2(*(__half2*)&u.z);
    float2 f3 = __half22float2(*(__half2*)&u.w);
    a0.x += f0.x; a0.y += f0.y; a0.z += f1.x; a0.w += f1.y;
    a1.x += f2.x; a1.y += f2.y; a1.z += f3.x; a1.w += f3.y;
}

__global__ void gather_h_kernel(const __half* __restrict__ xin,
                                __half* __restrict__ hout, int N) {
    PDL_WAIT();
    int lane = threadIdx.x & 31;
    int sub = lane >> 4;
    int sl = lane & 15;
    long long node = (long long)((blockIdx.x * (unsigned)blockDim.x + threadIdx.x) >> 5) * 2 + sub;
    if (node >= N) return;
    const uint4* x4 = (const uint4*)xin;
    float4 a0 = make_float4(0.f, 0.f, 0.f, 0.f);
    float4 a1 = make_float4(0.f, 0.f, 0.f, 0.f);
    acc_add4(a0, a1, __ldg(x4 + node * 16 + sl));
    int beg = __ldg(g_rowptr + node);
    int end = __ldg(g_rowptr + node + 1);
    int i = beg;
    for (; i + 4 <= end; i += 4) {
        int s0 = __ldg(g_elist + i);
        int s1 = __ldg(g_elist + i + 1);
        int s2 = __ldg(g_elist + i + 2);
        int s3 = __ldg(g_elist + i + 3);
        uint4 v0 = __ldg(x4 + (long long)s0 * 16 + sl);
        uint4 v1 = __ldg(x4 + (long long)s1 * 16 + sl);
        uint4 v2 = __ldg(x4 + (long long)s2 * 16 + sl);
        uint4 v3 = __ldg(x4 + (long long)s3 * 16 + sl);
        acc_add4(a0, a1, v0); acc_add4(a0, a1, v1);
        acc_add4(a0, a1, v2); acc_add4(a0, a1, v3);
    }
    for (; i < end; i++) {
        int s0 = __ldg(g_elist + i);
        acc_add4(a0, a1, __ldg(x4 + (long long)s0 * 16 + sl));
    }
    __half2 h0 = __floats2half2_rn(a0.x, a0.y);
    __half2 h1 = __floats2half2_rn(a0.z, a0.w);
    __half2 h2 = __floats2half2_rn(a1.x, a1.y);
    __half2 h3 = __floats2half2_rn(a1.z, a1.w);
    uint4 u;
    u.x = *(unsigned*)&h0;
    u.y = *(unsigned*)&h1;
    u.z = *(unsigned*)&h2;
    u.w = *(unsigned*)&h3;
    ((uint4*)hout)[node * 16 + sl] = u;
    PDL_TRIGGER();
}

// ---------------------------------------------------------------------------
// Fused layer (register-resident): out = relu(X@W1^T+b1)@W2^T+b2.
#define XSTR 136
#define WSTR 136
#define TR 128

__device__ __forceinline__ void mma_16x8x16(float* d, const unsigned* a, const unsigned* b) {
    asm volatile(
        "mma.sync.aligned.m16n8k16.row.col.f32.f16.f16.f32 "
        "{%0,%1,%2,%3}, {%4,%5,%6,%7}, {%8,%9}, {%0,%1,%2,%3};"
        : "+f"(d[0]), "+f"(d[1]), "+f"(d[2]), "+f"(d[3])
        : "r"(a[0]), "r"(a[1]), "r"(a[2]), "r"(a[3]), "r"(b[0]), "r"(b[1]));
}

__device__ __forceinline__ void ldsm_x4(unsigned& r0, unsigned& r1,
                                        unsigned& r2, unsigned& r3, unsigned addr) {
    asm volatile("ldmatrix.sync.aligned.m8n8.x4.shared.b16 {%0,%1,%2,%3}, [%4];"
                 : "=r"(r0), "=r"(r1), "=r"(r2), "=r"(r3) : "r"(addr));
}

__global__ __launch_bounds__(256, 1)
void layer_fused_kernel(const __half* __restrict__ in,
                        const __half* __restrict__ w1,   // [c][k]
                        const float* __restrict__ b1,
                        const __half* __restrict__ w2,   // [c][k]
                        const float* __restrict__ b2,
                        __half* __restrict__ outh,
                        float* __restrict__ outf,
                        int nrows) {
    extern __shared__ __half smh[];
    __half* Ws1 = smh;                        // [128][WSTR]
    __half* Ws2 = smh + 128 * WSTR;           // [128][WSTR]
    __half* Xs0 = smh + 2 * 128 * WSTR;       // [128][XSTR]
    __half* Xs1 = Xs0 + TR * XSTR;
    float*  Bs1 = (float*)(Xs1 + TR * XSTR);  // [128]
    float*  Bs2 = Bs1 + 128;                  // [128]

    int tid = threadIdx.x;

    // Preamble before wait (overlaps predecessor tail)
    for (int i = tid; i < 128 * 16; i += 256) {
        int c = i >> 4, seg = i & 15;
        *(uint4*)(Ws1 + c * WSTR + seg * 8) = __ldg((const uint4*)w1 + i);
        *(uint4*)(Ws2 + c * WSTR + seg * 8) = __ldg((const uint4*)w2 + i);
    }
    if (tid < 128) {
        Bs1[tid] = __ldg(b1 + tid);
        Bs2[tid] = __ldg(b2 + tid);
    }
    PDL_WAIT();

    int warp = tid >> 5, lane = tid & 31;
    int gi = lane >> 2, ti = lane & 3;
    int mbase = warp * 16;

    int a_row = mbase + (lane & 7) + (((lane >> 3) & 1) << 3);
    int a_koff = (lane >> 4) << 3;
    int b_row = (lane & 7) + ((lane >> 4) << 3);
    int b_koff = ((lane >> 3) & 1) << 3;

    unsigned ws1_base = (unsigned)__cvta_generic_to_shared(Ws1);
    unsigned ws2_base = (unsigned)__cvta_generic_to_shared(Ws2);
    unsigned xs0_base = (unsigned)__cvta_generic_to_shared(Xs0);
    unsigned xs1_base = (unsigned)__cvta_generic_to_shared(Xs1);
    unsigned b_off = (b_row * WSTR + b_koff) * 2;
    unsigned a_off = (a_row * XSTR + a_koff) * 2;

    int ntiles = (nrows + TR - 1) / TR;
    int stride = gridDim.x;

    uint4 reg[8];

    {
        long long r0 = (long long)blockIdx.x * TR;
#pragma unroll
        for (int p = 0; p < 8; p++) {
            int idx = tid + 256 * p;
            long long gr = r0 + (idx >> 4);
            reg[p] = (gr < nrows) ? __ldg((const uint4*)in + gr * 16 + (idx & 15))
                                  : make_uint4(0, 0, 0, 0);
        }
#pragma unroll
        for (int p = 0; p < 8; p++) {
            int idx = tid + 256 * p;
            *(uint4*)(Xs0 + (idx >> 4) * XSTR + (idx & 15) * 8) = reg[p];
        }
    }
    __syncthreads();

    unsigned xbase[2] = {xs0_base, xs1_base};
    __half* bufs[2] = {Xs0, Xs1};
    int buf = 0;

    for (int tt = blockIdx.x; tt < ntiles; tt += stride) {
        int nxt = tt + stride;
        if (nxt < ntiles) {
            long long r0 = (long long)nxt * TR;
#pragma unroll
            for (int p = 0; p < 8; p++) {
                int idx = tid + 256 * p;
                long long gr = r0 + (idx >> 4);
                reg[p] = (gr < nrows) ? __ldg((const uint4*)in + gr * 16 + (idx & 15))
                                      : make_uint4(0, 0, 0, 0);
            }
        }

        unsigned xs = xbase[buf];

        float acc1[16][4];
#pragma unroll
        for (int j = 0; j < 16; j++)
#pragma unroll
            for (int q = 0; q < 4; q++) acc1[j][q] = 0.f;

#pragma unroll
        for (int kk = 0; kk < 8; kk++) {
            int k0 = kk * 16;
            unsigned a[4];
            ldsm_x4(a[0], a[1], a[2], a[3], xs + a_off + k0 * 2);
#pragma unroll
            for (int j = 0; j < 16; j += 2) {
                unsigned r0, r1, r2, r3;
                ldsm_x4(r0, r1, r2, r3, ws1_base + b_off + (j * 8 * WSTR + k0) * 2);
                unsigned bj0[2] = {r0, r1};
                unsigned bj1[2] = {r2, r3};
                mma_16x8x16(acc1[j], a, bj0);
                mma_16x8x16(acc1[j + 1], a, bj1);
            }
        }

        unsigned af[16][2];
#pragma unroll
        for (int j = 0; j < 16; j++) {
            int c0 = j * 8 + 2 * ti;
            float bx = Bs1[c0], by = Bs1[c0 + 1];
            float v0 = fmaxf(acc1[j][0] + bx, 0.f);
            float v1 = fmaxf(acc1[j][1] + by, 0.f);
            float v2 = fmaxf(acc1[j][2] + bx, 0.f);
            float v3 = fmaxf(acc1[j][3] + by, 0.f);
            __half2 lo = __floats2half2_rn(v0, v1);
            __half2 hi = __floats2half2_rn(v2, v3);
            af[j][0] = *(unsigned*)&lo;
            af[j][1] = *(unsigned*)&hi;
        }

        float acc2[16][4];
#pragma unroll
        for (int j = 0; j < 16; j++)
#pragma unroll
            for (int q = 0; q < 4; q++) acc2[j][q] = 0.f;

#pragma unroll
        for (int kk = 0; kk < 8; kk++) {
            int k0 = kk * 16;
            unsigned a[4] = {af[2 * kk][0], af[2 * kk][1],
                             af[2 * kk + 1][0], af[2 * kk + 1][1]};
#pragma unroll
            for (int j = 0; j < 16; j += 2) {
                unsigned r0, r1, r2, r3;
                ldsm_x4(r0, r1, r2, r3, ws2_base + b_off + (j * 8 * WSTR + k0) * 2);
                unsigned bj0[2] = {r0, r1};
                unsigned bj1[2] = {r2, r3};
                mma_16x8x16(acc2[j], a, bj0);
                mma_16x8x16(acc2[j + 1], a, bj1);
            }
        }

        long long row0 = (long long)tt * TR + mbase + gi;
#pragma unroll
        for (int j = 0; j < 16; j++) {
            int c0 = j * 8 + 2 * ti;
            float bx = Bs2[c0], by = Bs2[c0 + 1];
            float v0 = acc2[j][0] + bx;
            float v1 = acc2[j][1] + by;
            float v2 = acc2[j][2] + bx;
            float v3 = acc2[j][3] + by;
            if (outf) {
                if (row0 < nrows)
                    *(float2*)(outf + row0 * D + c0) = make_float2(v0, v1);
                if (row0 + 8 < nrows)
                    *(float2*)(outf + (row0 + 8) * D + c0) = make_float2(v2, v3);
            } else {
                if (row0 < nrows)
                    *(__half2*)(outh + row0 * D + c0) = __floats2half2_rn(v0, v1);
                if (row0 + 8 < nrows)
                    *(__half2*)(outh + (row0 + 8) * D + c0) = __floats2half2_rn(v2, v3);
            }
        }

        if (nxt < ntiles) {
#pragma unroll
            for (int p = 0; p < 8; p++) {
                int idx = tid + 256 * p;
                *(uint4*)(bufs[buf ^ 1] + (idx >> 4) * XSTR + (idx & 15) * 8) = reg[p];
            }
            __syncthreads();
            buf ^= 1;
        }
    }
    PDL_TRIGGER();
}

// ---------------------------------------------------------------------------
template <typename... Args>
static void pdl_launch(void (*kern)(Args...), int grid, int block, size_t smem,
                       Args... args) {
    cudaLaunchAttribute attr;
    attr.id = cudaLaunchAttributeProgrammaticStreamSerialization;
    attr.val.programmaticStreamSerializationAllowed = 1;
    cudaLaunchConfig_t cfg = {};
    cfg.gridDim = dim3((unsigned)grid);
    cfg.blockDim = dim3((unsigned)block);
    cfg.dynamicSmemBytes = smem;
    cfg.stream = 0;
    cfg.attrs = &attr;
    cfg.numAttrs = 1;
    cudaLaunchKernelEx(&cfg, kern, args...);
}

extern "C" void kernel_launch(void* const* d_in, const int* in_sizes, int n_in,
                              void* d_out, int out_size) {
    const float* x   = (const float*)d_in[0];
    const int*   ei  = (const int*)d_in[1];
    const float* w0a = (const float*)d_in[2];
    const float* b0a = (const float*)d_in[3];
    const float* w0b = (const float*)d_in[4];
    const float* b0b = (const float*)d_in[5];
    const float* w1a = (const float*)d_in[6];
    const float* b1a = (const float*)d_in[7];
    const float* w1b = (const float*)d_in[8];
    const float* b1b = (const float*)d_in[9];

    int N = in_sizes[0] / D;
    int E = in_sizes[1] / 2;

    __half *p_xh, *p_hh, *p_oh, *p_wh;
    cudaGetSymbolAddress((void**)&p_xh, g_xh);
    cudaGetSymbolAddress((void**)&p_hh, g_hh);
    cudaGetSymbolAddress((void**)&p_oh, g_oh);
    cudaGetSymbolAddress((void**)&p_wh, g_wh);

    int nsm = 148;
    cudaDeviceGetAttribute(&nsm, cudaDevAttrMultiProcessorCount, 0);

    const size_t smem = (2 * 128 * WSTR + 2 * TR * XSTR) * sizeof(__half)
                      + 256 * sizeof(float);
    cudaFuncSetAttribute(layer_fused_kernel, cudaFuncAttributeMaxDynamicSharedMemorySize,
                         (int)smem);

    int nb = (N + 1023) / 1024;
    int gatherBlocks = (N + 15) / 16;
    int n4 = N * (D / 4);
    int e4 = (E + 3) / 4;
    int prepTotal = 4 * D * D + n4;
    int mergedTotal = (prepTotal > e4) ? prepTotal : e4;

    prep_hist_kernel<<<(mergedTotal + 255) / 256, 256>>>(x, w0a, w0b, w1a, w1b,
                                                         ei, n4, E, e4);

    pdl_launch(scan_fused_kernel, nb, 1024, (size_t)0, N, E);
    pdl_launch(fill_kernel, (e4 + 255) / 256, 256, (size_t)0, ei, E);

    // ---- Layer 1 ----
    pdl_launch(gather_h_kernel, gatherBlocks, 256, (size_t)0,
               (const __half*)p_xh, (__half*)p_hh, N);
    pdl_launch(layer_fused_kernel, nsm, 256, smem,
               (const __half*)p_hh, (const __half*)(p_wh + 0 * D * D), b0a,
               (const __half*)(p_wh + 1 * D * D), b0b,
               (__half*)p_oh, (float*)nullptr, N);

    // ---- Layer 2 ----
    pdl_launch(gather_h_kernel, gatherBlocks, 256, (size_t)0,
               (const __half*)p_oh, (__half*)p_hh, N);
    pdl_launch(layer_fused_kernel, nsm, 256, smem,
               (const __half*)p_hh, (const __half*)(p_wh + 2 * D * D), b1a,
               (const __half*)(p_wh + 3 * D * D), b1b,
               (__half*)nullptr, (float*)d_out, N);
}